// round 7
// baseline (speedup 1.0000x reference)
#include <cuda_runtime.h>
#include <cuda_bf16.h>
#include <math.h>
#include <stdint.h>

// Problem constants
#define T_DIM 2048
#define B_DIM 2
#define E_DIM 1024
#define H_DIM 16
#define DH    64
#define MROWS (T_DIM * B_DIM)   // 4096
#define NELEM (MROWS * E_DIM)   // 4194304

// Scratch: split-bf16 operands (device globals — no allocation allowed)
__device__ __nv_bfloat16 gXh[NELEM], gXl[NELEM];           // input X split
__device__ __nv_bfloat16 gWh[NELEM], gWl[NELEM];           // Wq,Wk,Wv,Wo (1M each)
__device__ __nv_bfloat16 gQh[NELEM], gQl[NELEM];
__device__ __nv_bfloat16 gKh[NELEM], gKl[NELEM];
__device__ __nv_bfloat16 gVh[NELEM], gVl[NELEM];
__device__ __nv_bfloat16 gAh[NELEM], gAl[NELEM];           // attn output split

// ===========================================================================
// Helpers
// ===========================================================================
__device__ __forceinline__ uint32_t smem_u32(const void* p) {
    uint32_t a;
    asm("{ .reg .u64 t; cvta.to.shared.u64 t, %1; cvt.u32.u64 %0, t; }" : "=r"(a) : "l"(p));
    return a;
}

#define LDSM4(R0, R1, R2, R3, ADDR) \
    asm volatile("ldmatrix.sync.aligned.m8n8.x4.shared.b16 {%0,%1,%2,%3}, [%4];" \
                 : "=r"(R0), "=r"(R1), "=r"(R2), "=r"(R3) : "r"(ADDR))

#define LDSM4T(R0, R1, R2, R3, ADDR) \
    asm volatile("ldmatrix.sync.aligned.m8n8.x4.trans.shared.b16 {%0,%1,%2,%3}, [%4];" \
                 : "=r"(R0), "=r"(R1), "=r"(R2), "=r"(R3) : "r"(ADDR))

#define MMA_BF16(D, A, B0, B1) \
    asm volatile("mma.sync.aligned.m16n8k16.row.col.f32.bf16.bf16.f32 " \
                 "{%0,%1,%2,%3}, {%4,%5,%6,%7}, {%8,%9}, {%0,%1,%2,%3};" \
                 : "+f"((D)[0]), "+f"((D)[1]), "+f"((D)[2]), "+f"((D)[3]) \
                 : "r"((A)[0]), "r"((A)[1]), "r"((A)[2]), "r"((A)[3]), "r"(B0), "r"(B1))

#define CP_ASYNC16(DST, SRC) \
    asm volatile("cp.async.cg.shared.global [%0], [%1], 16;" :: "r"(DST), "l"(SRC) : "memory")
#define CP_COMMIT() asm volatile("cp.async.commit_group;" ::: "memory")
#define CP_WAIT(N)  asm volatile("cp.async.wait_group %0;" :: "n"(N) : "memory")

// pack two f32 into bf16x2 hi + residual lo
__device__ __forceinline__ void split_pack(float a, float b, uint32_t& hi, uint32_t& lo) {
    __nv_bfloat162 H, L;
    H.x = __float2bfloat16(a); H.y = __float2bfloat16(b);
    L.x = __float2bfloat16(a - __bfloat162float(H.x));
    L.y = __float2bfloat16(b - __bfloat162float(H.y));
    hi = *(uint32_t*)&H; lo = *(uint32_t*)&L;
}

// fast exp on FMA pipe (no MUFU)
__device__ __forceinline__ float fast_exp(float x) {
    float y = fmaxf(x * 1.44269504f, -126.0f);
    int   e = __float2int_rn(y);
    float f = y - (float)e;
    float p = 1.33336e-3f;
    p = fmaf(p, f, 9.61812e-3f);
    p = fmaf(p, f, 5.55041e-2f);
    p = fmaf(p, f, 2.402265e-1f);
    p = fmaf(p, f, 6.931472e-1f);
    p = fmaf(p, f, 1.0f);
    return __int_as_float((e + 127) << 23) * p;
}

// ===========================================================================
// Convert kernel: split X and the 4 weight matrices into hi/lo bf16 globals.
// ===========================================================================
__global__ void __launch_bounds__(256)
convert_kernel(const float* __restrict__ X,
               const float* __restrict__ Wq, const float* __restrict__ Wk,
               const float* __restrict__ Wv, const float* __restrict__ Wo)
{
    int i = blockIdx.x * 256 + threadIdx.x;       // 0 .. 2097151
    const float4* src;
    __nv_bfloat16 *dh, *dl;
    int off;
    if (i < 1048576) {
        src = (const float4*)X; dh = gXh; dl = gXl; off = i;
    } else {
        int j = i - 1048576;
        int r = j >> 18;                           // 0..3 -> Wq,Wk,Wv,Wo
        off = j & 0x3FFFF;
        src = (const float4*)(r == 0 ? Wq : r == 1 ? Wk : r == 2 ? Wv : Wo);
        dh = gWh + ((size_t)r << 20);
        dl = gWl + ((size_t)r << 20);
    }
    float4 v = src[off];
    uint32_t h01, l01, h23, l23;
    split_pack(v.x, v.y, h01, l01);
    split_pack(v.z, v.w, h23, l23);
    *(uint2*)(dh + (size_t)off * 4) = make_uint2(h01, h23);
    *(uint2*)(dl + (size_t)off * 4) = make_uint2(l01, l23);
}

// ===========================================================================
// GEMM on tensor cores: C = (A @ W^T + bias) * alpha, split-bf16 operands.
// CTA 128x128, 4 warps (2x2), warp tile 64x64, BK=32, 2-stage cp.async,
// one barrier per chunk, 2 CTAs/SM.
// ===========================================================================
#define GPITCH 40
#define GARR_E (128 * GPITCH)          // 5120 elems per array
#define GSTAGE_E (4 * GARR_E)          // 20480 elems per stage
#define GSMEM_BYTES (2 * GSTAGE_E * 2)   // 81920
#define GTHR 128

__device__ __forceinline__ void gemm_produce(
    uint32_t smb, int stage,
    const __nv_bfloat16* __restrict__ Ah, const __nv_bfloat16* __restrict__ Al,
    const __nv_bfloat16* __restrict__ Bh, const __nv_bfloat16* __restrict__ Bl,
    int row0, int col0, int k0, int tid)
{
#pragma unroll
    for (int i = 0; i < 16; ++i) {
        int id  = tid + i * GTHR;        // 0..2047
        int arr = id >> 9;               // 0:Ah 1:Al 2:Bh 3:Bl
        int rid = (id >> 2) & 127;
        int cc  = id & 3;
        const __nv_bfloat16* g = (arr == 0) ? Ah : (arr == 1) ? Al : (arr == 2) ? Bh : Bl;
        int grow = ((arr < 2) ? row0 : col0) + rid;
        const __nv_bfloat16* src = g + (size_t)grow * E_DIM + k0 + cc * 8;
        uint32_t dst = smb + (uint32_t)(stage * GSTAGE_E + arr * GARR_E + rid * GPITCH + cc * 8) * 2;
        CP_ASYNC16(dst, src);
    }
}

template <int MODE>
__device__ __forceinline__ void gemm_cp(
    const __nv_bfloat16* __restrict__ Ah, const __nv_bfloat16* __restrict__ Al,
    const __nv_bfloat16* __restrict__ Bh, const __nv_bfloat16* __restrict__ Bl,
    const float* __restrict__ bias, float alpha,
    float* __restrict__ Cf,
    __nv_bfloat16* __restrict__ Ch, __nv_bfloat16* __restrict__ Cl)
{
    extern __shared__ char dynsm[];
    const uint32_t smb = smem_u32(dynsm);
    const int tid  = threadIdx.x;
    const int lane = tid & 31;
    const int wid  = tid >> 5;           // 0..3
    const int wy   = wid >> 1;           // 0..1 -> 64 rows each
    const int wx   = wid & 1;            // 0..1 -> 64 cols each
    const int row0 = blockIdx.y * 128;
    const int col0 = blockIdx.x * 128;

    const int aOffE = (wy * 64 + (lane & 15)) * GPITCH + ((lane >> 4) & 1) * 8;
    const int bOffE = (wx * 64 + (lane & 7) + ((lane >> 4) & 1) * 8) * GPITCH + ((lane >> 3) & 1) * 8;

    float acc[4][8][4];
#pragma unroll
    for (int i = 0; i < 4; i++)
#pragma unroll
        for (int j = 0; j < 8; j++)
#pragma unroll
            for (int k = 0; k < 4; k++) acc[i][j][k] = 0.f;

    // prologue: stage 0 <- chunk 0
    gemm_produce(smb, 0, Ah, Al, Bh, Bl, row0, col0, 0, tid);
    CP_COMMIT();

    for (int c = 0; c < 32; ++c) {
        CP_WAIT(0);          // chunk c landed (issued one full compute phase ago)
        __syncthreads();     // visible to all warps; prev stage reads done
        if (c + 1 < 32) {
            gemm_produce(smb, (c + 1) & 1, Ah, Al, Bh, Bl, row0, col0, (c + 1) * 32, tid);
            CP_COMMIT();
        }

        const uint32_t stA = smb + (uint32_t)((c & 1) * GSTAGE_E) * 2;
        const uint32_t aHb = stA;
        const uint32_t aLb = stA + GARR_E * 2;
        const uint32_t bHb = stA + 2 * GARR_E * 2;
        const uint32_t bLb = stA + 3 * GARR_E * 2;

#pragma unroll
        for (int kb = 0; kb < 2; ++kb) {
            uint32_t bh[4][4], bl[4][4];
#pragma unroll
            for (int nb = 0; nb < 4; ++nb) {           // n16 groups (64 cols)
                int boe = bOffE + nb * 16 * GPITCH + kb * 16;
                LDSM4(bh[nb][0], bh[nb][1], bh[nb][2], bh[nb][3], bHb + boe * 2);
                LDSM4(bl[nb][0], bl[nb][1], bl[nb][2], bl[nb][3], bLb + boe * 2);
            }
#pragma unroll
            for (int mf = 0; mf < 4; ++mf) {
                uint32_t ah[4], al[4];
                int aoe = aOffE + mf * 16 * GPITCH + kb * 16;
                LDSM4(ah[0], ah[1], ah[2], ah[3], aHb + aoe * 2);
                LDSM4(al[0], al[1], al[2], al[3], aLb + aoe * 2);
                // term-major: same-accumulator distance = 8
#pragma unroll
                for (int nb = 0; nb < 4; ++nb) {
                    MMA_BF16(acc[mf][2 * nb],     ah, bh[nb][0], bh[nb][1]);
                    MMA_BF16(acc[mf][2 * nb + 1], ah, bh[nb][2], bh[nb][3]);
                }
#pragma unroll
                for (int nb = 0; nb < 4; ++nb) {
                    MMA_BF16(acc[mf][2 * nb],     ah, bl[nb][0], bl[nb][1]);
                    MMA_BF16(acc[mf][2 * nb + 1], ah, bl[nb][2], bl[nb][3]);
                }
#pragma unroll
                for (int nb = 0; nb < 4; ++nb) {
                    MMA_BF16(acc[mf][2 * nb],     al, bh[nb][0], bh[nb][1]);
                    MMA_BF16(acc[mf][2 * nb + 1], al, bh[nb][2], bh[nb][3]);
                }
            }
        }
    }

    // epilogue
#pragma unroll
    for (int mf = 0; mf < 4; ++mf) {
        int r = row0 + wy * 64 + mf * 16 + (lane >> 2);
#pragma unroll
        for (int nf = 0; nf < 8; ++nf) {
            int col = col0 + wx * 64 + nf * 8 + ((lane & 3) << 1);
            float b0 = bias[col], b1 = bias[col + 1];
            float v0 = (acc[mf][nf][0] + b0) * alpha;
            float v1 = (acc[mf][nf][1] + b1) * alpha;
            float v2 = (acc[mf][nf][2] + b0) * alpha;
            float v3 = (acc[mf][nf][3] + b1) * alpha;
            if (MODE == 0) {
                *(float2*)(Cf + (size_t)r * E_DIM + col)       = make_float2(v0, v1);
                *(float2*)(Cf + (size_t)(r + 8) * E_DIM + col) = make_float2(v2, v3);
            } else {
                uint32_t h01, l01, h23, l23;
                split_pack(v0, v1, h01, l01);
                split_pack(v2, v3, h23, l23);
                *(uint32_t*)(Ch + (size_t)r * E_DIM + col)       = h01;
                *(uint32_t*)(Cl + (size_t)r * E_DIM + col)       = l01;
                *(uint32_t*)(Ch + (size_t)(r + 8) * E_DIM + col) = h23;
                *(uint32_t*)(Cl + (size_t)(r + 8) * E_DIM + col) = l23;
            }
        }
    }
}

__global__ void __launch_bounds__(GTHR, 2)
qkv_kernel(const float* __restrict__ bq, const float* __restrict__ bk,
           const float* __restrict__ bv)
{
    const int z = blockIdx.z;
    const __nv_bfloat16* Bh = gWh + ((size_t)z << 20);
    const __nv_bfloat16* Bl = gWl + ((size_t)z << 20);
    if (z == 0)      gemm_cp<1>(gXh, gXl, Bh, Bl, bq, 0.125f, nullptr, gQh, gQl);
    else if (z == 1) gemm_cp<1>(gXh, gXl, Bh, Bl, bk, 1.0f,   nullptr, gKh, gKl);
    else             gemm_cp<1>(gXh, gXl, Bh, Bl, bv, 1.0f,   nullptr, gVh, gVl);
}

__global__ void __launch_bounds__(GTHR, 2)
oproj_kernel(const float* __restrict__ bo, float* __restrict__ out)
{
    gemm_cp<0>(gAh, gAl, gWh + ((size_t)3 << 20), gWl + ((size_t)3 << 20),
               bo, 1.0f, out, nullptr, nullptr);
}

// ===========================================================================
// Flash attention on tensor cores (causal), split-bf16 inputs via cp.async.
// BR=128 (8 warps x m16), BC=64, Dh=64. Double-buffered K/V tiles.
// Balanced q-tile pairs; single barrier per kv-tile.
// ===========================================================================
#define FPITCH 72
#define FQ_E   (128 * FPITCH)              // 9216 per Q array
#define FKV_E  (64 * FPITCH)               // 4608 per KV array
#define FSTAGE_E (4 * FKV_E)               // 18432 per stage
#define FKV0_E (2 * FQ_E)                  // 18432 (stage area starts here)
#define FSMEM_BYTES ((FKV0_E + 2 * FSTAGE_E) * 2)   // 110592

__device__ __forceinline__ void flash_kv_produce(uint32_t smb, int stage, int j0,
                                                 int b, int colbase, int tid)
{
#pragma unroll
    for (int i = 0; i < 8; ++i) {
        int id  = tid + i * 256;
        int arr = id >> 9;                // 0:Kh 1:Kl 2:Vh 3:Vl
        int rid = (id >> 3) & 63;
        int cc  = id & 7;
        const __nv_bfloat16* g = (arr == 0) ? gKh : (arr == 1) ? gKl : (arr == 2) ? gVh : gVl;
        const __nv_bfloat16* src = g + ((size_t)(j0 + rid) * B_DIM + b) * E_DIM + colbase + cc * 8;
        uint32_t dst = smb + (uint32_t)(FKV0_E + stage * FSTAGE_E + arr * FKV_E + rid * FPITCH + cc * 8) * 2;
        CP_ASYNC16(dst, src);
    }
}

__device__ __forceinline__ void flash_one(int qt, uint32_t smb, int b, int colbase,
                                          int tid, int lane, int w,
                                          int qOffE, int kOffE, int vOffE)
{
    const int i0 = qt * 128;
    const int ktmax = 2 * qt + 1;

    // prologue: Q tile (both splits) + KV stage 0 in one cp.async group
#pragma unroll
    for (int i = 0; i < 8; ++i) {
        int id  = tid + i * 256;          // 0..2047
        int arr = id >> 10;               // 0:Qh 1:Ql
        int rid = (id >> 3) & 127;
        int cc  = id & 7;
        const __nv_bfloat16* g = arr ? gQl : gQh;
        const __nv_bfloat16* src = g + ((size_t)(i0 + rid) * B_DIM + b) * E_DIM + colbase + cc * 8;
        uint32_t dst = smb + (uint32_t)(arr * FQ_E + rid * FPITCH + cc * 8) * 2;
        CP_ASYNC16(dst, src);
    }
    flash_kv_produce(smb, 0, 0, b, colbase, tid);
    CP_COMMIT();

    float s_m[2] = {-1e9f, -1e9f};
    float s_l[2] = {0.f, 0.f};
    float o[8][4];
#pragma unroll
    for (int i = 0; i < 8; i++)
#pragma unroll
        for (int j = 0; j < 4; j++) o[i][j] = 0.f;

    const int rg0 = i0 + w * 16 + (lane >> 2);
    const uint32_t qhB = smb;
    const uint32_t qlB = smb + FQ_E * 2;

    for (int kt = 0; kt <= ktmax; ++kt) {
        CP_WAIT(0);           // tile kt landed (issued one compute phase ago)
        __syncthreads();      // visible to all; prev stage reads done
        if (kt + 1 <= ktmax) {
            flash_kv_produce(smb, (kt + 1) & 1, (kt + 1) * 64, b, colbase, tid);
            CP_COMMIT();
        }

        const int j0 = kt * 64;
        const uint32_t stKV = smb + (uint32_t)(FKV0_E + (kt & 1) * FSTAGE_E) * 2;
        const uint32_t khB = stKV;
        const uint32_t klB = stKV + FKV_E * 2;
        const uint32_t vhB = stKV + 2 * FKV_E * 2;
        const uint32_t vlB = stKV + 3 * FKV_E * 2;

        // ---- S = Q @ K^T (term-major) ----
        float s[8][4];
#pragma unroll
        for (int i = 0; i < 8; i++)
#pragma unroll
            for (int j = 0; j < 4; j++) s[i][j] = 0.f;

#pragma unroll
        for (int kb = 0; kb < 4; ++kb) {
            uint32_t a0[4], a1[4];
            int aoe = qOffE + kb * 16;
            LDSM4(a0[0], a0[1], a0[2], a0[3], qhB + aoe * 2);
            LDSM4(a1[0], a1[1], a1[2], a1[3], qlB + aoe * 2);
            uint32_t bh[4][4], bl[4][4];
#pragma unroll
            for (int np = 0; np < 4; ++np) {
                int boe = kOffE + np * 16 * FPITCH + kb * 16;
                LDSM4(bh[np][0], bh[np][1], bh[np][2], bh[np][3], khB + boe * 2);
                LDSM4(bl[np][0], bl[np][1], bl[np][2], bl[np][3], klB + boe * 2);
            }
#pragma unroll
            for (int np = 0; np < 4; ++np) {
                MMA_BF16(s[2 * np],     a0, bh[np][0], bh[np][1]);
                MMA_BF16(s[2 * np + 1], a0, bh[np][2], bh[np][3]);
            }
#pragma unroll
            for (int np = 0; np < 4; ++np) {
                MMA_BF16(s[2 * np],     a0, bl[np][0], bl[np][1]);
                MMA_BF16(s[2 * np + 1], a0, bl[np][2], bl[np][3]);
            }
#pragma unroll
            for (int np = 0; np < 4; ++np) {
                MMA_BF16(s[2 * np],     a1, bh[np][0], bh[np][1]);
                MMA_BF16(s[2 * np + 1], a1, bh[np][2], bh[np][3]);
            }
        }

        // ---- causal mask ----
        if (j0 + 63 > i0 + w * 16) {
#pragma unroll
            for (int nf = 0; nf < 8; ++nf) {
                int j = j0 + nf * 8 + ((lane & 3) << 1);
                if (j     > rg0)     s[nf][0] = -1e9f;
                if (j + 1 > rg0)     s[nf][1] = -1e9f;
                if (j     > rg0 + 8) s[nf][2] = -1e9f;
                if (j + 1 > rg0 + 8) s[nf][3] = -1e9f;
            }
        }

        // ---- online softmax ----
#pragma unroll
        for (int half = 0; half < 2; ++half) {
            const int e0 = half * 2, e1 = half * 2 + 1;
            float vmax = -1e9f;
#pragma unroll
            for (int nf = 0; nf < 8; ++nf)
                vmax = fmaxf(vmax, fmaxf(s[nf][e0], s[nf][e1]));
            vmax = fmaxf(vmax, __shfl_xor_sync(0xffffffffu, vmax, 1));
            vmax = fmaxf(vmax, __shfl_xor_sync(0xffffffffu, vmax, 2));
            float mnew = fmaxf(s_m[half], vmax);
            float corr = fast_exp(s_m[half] - mnew);
            float rsum = 0.f;
#pragma unroll
            for (int nf = 0; nf < 8; ++nf) {
                s[nf][e0] = fast_exp(s[nf][e0] - mnew);
                s[nf][e1] = fast_exp(s[nf][e1] - mnew);
                rsum += s[nf][e0] + s[nf][e1];
            }
            rsum += __shfl_xor_sync(0xffffffffu, rsum, 1);
            rsum += __shfl_xor_sync(0xffffffffu, rsum, 2);
            s_l[half] = s_l[half] * corr + rsum;
            s_m[half] = mnew;
#pragma unroll
            for (int nf = 0; nf < 8; ++nf) {
                o[nf][e0] *= corr;
                o[nf][e1] *= corr;
            }
        }

        // ---- O += P @ V (term-major) ----
#pragma unroll
        for (int kc = 0; kc < 4; ++kc) {
            uint32_t ph[4], pl[4];
            split_pack(s[2 * kc][0],     s[2 * kc][1],     ph[0], pl[0]);
            split_pack(s[2 * kc][2],     s[2 * kc][3],     ph[1], pl[1]);
            split_pack(s[2 * kc + 1][0], s[2 * kc + 1][1], ph[2], pl[2]);
            split_pack(s[2 * kc + 1][2], s[2 * kc + 1][3], ph[3], pl[3]);
            uint32_t wh[4][4], wl[4][4];
#pragma unroll
            for (int np = 0; np < 4; ++np) {
                int voe = vOffE + kc * 16 * FPITCH + np * 16;
                LDSM4T(wh[np][0], wh[np][1], wh[np][2], wh[np][3], vhB + voe * 2);
                LDSM4T(wl[np][0], wl[np][1], wl[np][2], wl[np][3], vlB + voe * 2);
            }
#pragma unroll
            for (int np = 0; np < 4; ++np) {
                MMA_BF16(o[2 * np],     ph, wh[np][0], wh[np][1]);
                MMA_BF16(o[2 * np + 1], ph, wh[np][2], wh[np][3]);
            }
#pragma unroll
            for (int np = 0; np < 4; ++np) {
                MMA_BF16(o[2 * np],     pl, wh[np][0], wh[np][1]);
                MMA_BF16(o[2 * np + 1], pl, wh[np][2], wh[np][3]);
            }
#pragma unroll
            for (int np = 0; np < 4; ++np) {
                MMA_BF16(o[2 * np],     ph, wl[np][0], wl[np][1]);
                MMA_BF16(o[2 * np + 1], ph, wl[np][2], wl[np][3]);
            }
        }
    }
    __syncthreads();   // all smem reads done before caller refills Q region

    // ---- finalize: write split-bf16 attn for the O-projection ----
    const float inv0 = 1.f / s_l[0];
    const float inv1 = 1.f / s_l[1];
#pragma unroll
    for (int nf = 0; nf < 8; ++nf) {
        int col = colbase + nf * 8 + ((lane & 3) << 1);
        float v0 = o[nf][0] * inv0, v1 = o[nf][1] * inv0;
        float v2 = o[nf][2] * inv1, v3 = o[nf][3] * inv1;
        uint32_t h01, l01, h23, l23;
        split_pack(v0, v1, h01, l01);
        split_pack(v2, v3, h23, l23);
        size_t r0off = ((size_t)rg0 * B_DIM + b) * E_DIM + col;
        size_t r1off = ((size_t)(rg0 + 8) * B_DIM + b) * E_DIM + col;
        *(uint32_t*)(gAh + r0off) = h01;
        *(uint32_t*)(gAl + r0off) = l01;
        *(uint32_t*)(gAh + r1off) = h23;
        *(uint32_t*)(gAl + r1off) = l23;
    }
}

__global__ void __launch_bounds__(256)
flash_mma_kernel()
{
    extern __shared__ char dynsm[];
    const uint32_t smb = smem_u32(dynsm);

    const int tid  = threadIdx.x;
    const int lane = tid & 31;
    const int w    = tid >> 5;
    const int pair = blockIdx.x;          // 0..7
    const int head = blockIdx.y;          // 0..31
    const int b    = head >> 4;
    const int h    = head & 15;
    const int colbase = h * DH;

    const int qOffE = (w * 16 + (lane & 15)) * FPITCH + ((lane >> 4) & 1) * 8;
    const int kOffE = ((lane & 7) + ((lane >> 4) & 1) * 8) * FPITCH + ((lane >> 3) & 1) * 8;
    const int vOffE = ((lane & 7) + ((lane >> 3) & 1) * 8) * FPITCH + ((lane >> 4) & 1) * 8;

    // balanced pair: (pair) and (15 - pair) -> 34 kv-tiles per CTA, uniform
    flash_one(pair,      smb, b, colbase, tid, lane, w, qOffE, kOffE, vOffE);
    flash_one(15 - pair, smb, b, colbase, tid, lane, w, qOffE, kOffE, vOffE);
}

// ===========================================================================
// kernel_launch
// Inputs: query, Wq, bq, Wk, bk, Wv, bv, Wo, bo, attn_mask (ignored: causal)
// ===========================================================================
extern "C" void kernel_launch(void* const* d_in, const int* in_sizes, int n_in,
                              void* d_out, int out_size)
{
    const float* query = (const float*)d_in[0];
    const float* Wq    = (const float*)d_in[1];
    const float* bq    = (const float*)d_in[2];
    const float* Wk    = (const float*)d_in[3];
    const float* bk    = (const float*)d_in[4];
    const float* Wv    = (const float*)d_in[5];
    const float* bv    = (const float*)d_in[6];
    const float* Wo    = (const float*)d_in[7];
    const float* bo    = (const float*)d_in[8];
    float* out = (float*)d_out;

    cudaFuncSetAttribute(qkv_kernel, cudaFuncAttributeMaxDynamicSharedMemorySize, GSMEM_BYTES);
    cudaFuncSetAttribute(oproj_kernel, cudaFuncAttributeMaxDynamicSharedMemorySize, GSMEM_BYTES);
    cudaFuncSetAttribute(flash_mma_kernel, cudaFuncAttributeMaxDynamicSharedMemorySize, FSMEM_BYTES);

    // split X and weights to bf16 hi/lo
    convert_kernel<<<8192, 256>>>(query, Wq, Wk, Wv, Wo);

    // QKV projections (z selects Q/K/V), outputs split bf16
    qkv_kernel<<<dim3(E_DIM / 128, MROWS / 128, 3), GTHR, GSMEM_BYTES>>>(bq, bk, bv);

    // causal flash attention: 8 balanced q-tile pairs x 32 heads
    flash_mma_kernel<<<dim3(8, B_DIM * H_DIM), 256, FSMEM_BYTES>>>();

    // output projection -> f32 out
    oproj_kernel<<<dim3(E_DIM / 128, MROWS / 128), GTHR, GSMEM_BYTES>>>(bo, out);
}

// round 8
// speedup vs baseline: 1.5762x; 1.5762x over previous
#include <cuda_runtime.h>
#include <cuda_fp16.h>
#include <math.h>
#include <stdint.h>

// Problem constants
#define T_DIM 2048
#define B_DIM 2
#define E_DIM 1024
#define H_DIM 16
#define DH    64
#define MROWS (T_DIM * B_DIM)   // 4096
#define NELEM (MROWS * E_DIM)   // 4194304

// Scratch (device globals — no allocation allowed). All fp16.
__device__ __half gXh[NELEM], gXl[NELEM];   // input X split hi/lo
__device__ __half gW[NELEM];                // Wq,Wk,Wv,Wo hi only (1M each)
__device__ __half gQ[NELEM], gK[NELEM], gV[NELEM];   // single fp16
__device__ __half gAh[NELEM], gAl[NELEM];   // attn output split hi/lo

// ===========================================================================
// Helpers
// ===========================================================================
__device__ __forceinline__ uint32_t smem_u32(const void* p) {
    uint32_t a;
    asm("{ .reg .u64 t; cvta.to.shared.u64 t, %1; cvt.u32.u64 %0, t; }" : "=r"(a) : "l"(p));
    return a;
}

#define LDSM4(R0, R1, R2, R3, ADDR) \
    asm volatile("ldmatrix.sync.aligned.m8n8.x4.shared.b16 {%0,%1,%2,%3}, [%4];" \
                 : "=r"(R0), "=r"(R1), "=r"(R2), "=r"(R3) : "r"(ADDR))

#define LDSM4T(R0, R1, R2, R3, ADDR) \
    asm volatile("ldmatrix.sync.aligned.m8n8.x4.trans.shared.b16 {%0,%1,%2,%3}, [%4];" \
                 : "=r"(R0), "=r"(R1), "=r"(R2), "=r"(R3) : "r"(ADDR))

#define MMA_F16(D, A, B0, B1) \
    asm volatile("mma.sync.aligned.m16n8k16.row.col.f32.f16.f16.f32 " \
                 "{%0,%1,%2,%3}, {%4,%5,%6,%7}, {%8,%9}, {%0,%1,%2,%3};" \
                 : "+f"((D)[0]), "+f"((D)[1]), "+f"((D)[2]), "+f"((D)[3]) \
                 : "r"((A)[0]), "r"((A)[1]), "r"((A)[2]), "r"((A)[3]), "r"(B0), "r"(B1))

#define CP_ASYNC16(DST, SRC) \
    asm volatile("cp.async.cg.shared.global [%0], [%1], 16;" :: "r"(DST), "l"(SRC) : "memory")
#define CP_COMMIT() asm volatile("cp.async.commit_group;" ::: "memory")
#define CP_WAIT(N)  asm volatile("cp.async.wait_group %0;" :: "n"(N) : "memory")

__device__ __forceinline__ uint32_t pack_h2(float a, float b) {
    __half2 h;
    h.x = __float2half_rn(a); h.y = __float2half_rn(b);
    return *(uint32_t*)&h;
}

// split fp32 into fp16 hi + fp16 residual lo
__device__ __forceinline__ void split_h(float a, __half& hi, __half& lo) {
    hi = __float2half_rn(a);
    lo = __float2half_rn(a - __half2float(hi));
}

// fast exp on FMA pipe (no MUFU)
__device__ __forceinline__ float fast_exp(float x) {
    float y = fmaxf(x * 1.44269504f, -126.0f);
    int   e = __float2int_rn(y);
    float f = y - (float)e;
    float p = 1.33336e-3f;
    p = fmaf(p, f, 9.61812e-3f);
    p = fmaf(p, f, 5.55041e-2f);
    p = fmaf(p, f, 2.402265e-1f);
    p = fmaf(p, f, 6.931472e-1f);
    p = fmaf(p, f, 1.0f);
    return __int_as_float((e + 127) << 23) * p;
}

// ===========================================================================
// Convert: X -> fp16 hi/lo split; W's -> fp16 hi only.
// ===========================================================================
__global__ void __launch_bounds__(256)
convert_kernel(const float* __restrict__ X,
               const float* __restrict__ Wq, const float* __restrict__ Wk,
               const float* __restrict__ Wv, const float* __restrict__ Wo)
{
    int i = blockIdx.x * 256 + threadIdx.x;       // 0 .. 2097151
    if (i < 1048576) {
        float4 v = ((const float4*)X)[i];
        __half h0, h1, h2, h3, l0, l1, l2, l3;
        split_h(v.x, h0, l0); split_h(v.y, h1, l1);
        split_h(v.z, h2, l2); split_h(v.w, h3, l3);
        __half2 H01; H01.x = h0; H01.y = h1;
        __half2 H23; H23.x = h2; H23.y = h3;
        __half2 L01; L01.x = l0; L01.y = l1;
        __half2 L23; L23.x = l2; L23.y = l3;
        *(uint2*)(gXh + (size_t)i * 4) = make_uint2(*(uint32_t*)&H01, *(uint32_t*)&H23);
        *(uint2*)(gXl + (size_t)i * 4) = make_uint2(*(uint32_t*)&L01, *(uint32_t*)&L23);
    } else {
        int j = i - 1048576;
        int r = j >> 18;                           // 0..3 -> Wq,Wk,Wv,Wo
        int off = j & 0x3FFFF;
        const float4* src = (const float4*)(r == 0 ? Wq : r == 1 ? Wk : r == 2 ? Wv : Wo);
        float4 v = src[off];
        __half2 H01, H23;
        H01.x = __float2half_rn(v.x); H01.y = __float2half_rn(v.y);
        H23.x = __float2half_rn(v.z); H23.y = __float2half_rn(v.w);
        *(uint2*)(gW + ((size_t)r << 20) + (size_t)off * 4) =
            make_uint2(*(uint32_t*)&H01, *(uint32_t*)&H23);
    }
}

// ===========================================================================
// GEMM: C = ((Ah+Al) @ Wh^T + bias) * alpha   (2 fp16 MMA terms)
// CTA 128x128, 8 warps (2x4), warp 64x32, BK=32, 2-stage cp.async, 2 CTAs/SM.
// MODE 0: f32 out.  MODE 1: single-fp16 out.
// ===========================================================================
#define GPITCH 40
#define GARR_E (128 * GPITCH)            // 5120 elems per array
#define GSTAGE_E (3 * GARR_E)            // Ah, Al, Bh
#define GSMEM_BYTES (2 * GSTAGE_E * 2)   // 61440

__device__ __forceinline__ void gemm_produce(
    uint32_t smb, int stage,
    const __half* __restrict__ Ah, const __half* __restrict__ Al,
    const __half* __restrict__ Bh,
    int row0, int col0, int k0, int tid)
{
#pragma unroll
    for (int i = 0; i < 6; ++i) {
        int id  = tid + i * 256;         // 0..1535
        int arr = id >> 9;               // 0:Ah 1:Al 2:Bh
        int rid = (id >> 2) & 127;
        int cc  = id & 3;
        const __half* g = (arr == 0) ? Ah : (arr == 1) ? Al : Bh;
        int grow = ((arr < 2) ? row0 : col0) + rid;
        const __half* src = g + (size_t)grow * E_DIM + k0 + cc * 8;
        uint32_t dst = smb + (uint32_t)(stage * GSTAGE_E + arr * GARR_E + rid * GPITCH + cc * 8) * 2;
        CP_ASYNC16(dst, src);
    }
}

template <int MODE>
__device__ __forceinline__ void gemm_cp(
    const __half* __restrict__ Ah, const __half* __restrict__ Al,
    const __half* __restrict__ Bh,
    const float* __restrict__ bias, float alpha,
    float* __restrict__ Cf, __half* __restrict__ Ch)
{
    extern __shared__ char dynsm[];
    const uint32_t smb = smem_u32(dynsm);
    const int tid  = threadIdx.x;
    const int lane = tid & 31;
    const int wid  = tid >> 5;
    const int wy   = wid >> 2;           // 0..1
    const int wx   = wid & 3;            // 0..3
    const int row0 = blockIdx.y * 128;
    const int col0 = blockIdx.x * 128;

    const int aOffE = (wy * 64 + (lane & 15)) * GPITCH + ((lane >> 4) & 1) * 8;
    const int bOffE = (wx * 32 + (lane & 7) + ((lane >> 4) & 1) * 8) * GPITCH + ((lane >> 3) & 1) * 8;

    float acc[4][4][4];
#pragma unroll
    for (int i = 0; i < 4; i++)
#pragma unroll
        for (int j = 0; j < 4; j++)
#pragma unroll
            for (int k = 0; k < 4; k++) acc[i][j][k] = 0.f;

    gemm_produce(smb, 0, Ah, Al, Bh, row0, col0, 0, tid);
    CP_COMMIT();

    for (int c = 0; c < 32; ++c) {
        CP_WAIT(0);
        __syncthreads();
        if (c + 1 < 32) {
            gemm_produce(smb, (c + 1) & 1, Ah, Al, Bh, row0, col0, (c + 1) * 32, tid);
            CP_COMMIT();
        }

        const uint32_t stA = smb + (uint32_t)((c & 1) * GSTAGE_E) * 2;
        const uint32_t aHb = stA;
        const uint32_t aLb = stA + GARR_E * 2;
        const uint32_t bHb = stA + 2 * GARR_E * 2;

#pragma unroll
        for (int kb = 0; kb < 2; ++kb) {
            uint32_t bh[4][2];
#pragma unroll
            for (int np = 0; np < 2; ++np) {
                int boe = bOffE + np * 16 * GPITCH + kb * 16;
                LDSM4(bh[2 * np][0], bh[2 * np][1], bh[2 * np + 1][0], bh[2 * np + 1][1],
                      bHb + boe * 2);
            }
#pragma unroll
            for (int mf = 0; mf < 4; ++mf) {
                uint32_t ah[4], al[4];
                int aoe = aOffE + mf * 16 * GPITCH + kb * 16;
                LDSM4(ah[0], ah[1], ah[2], ah[3], aHb + aoe * 2);
                LDSM4(al[0], al[1], al[2], al[3], aLb + aoe * 2);
                MMA_F16(acc[mf][0], ah, bh[0][0], bh[0][1]);
                MMA_F16(acc[mf][1], ah, bh[1][0], bh[1][1]);
                MMA_F16(acc[mf][2], ah, bh[2][0], bh[2][1]);
                MMA_F16(acc[mf][3], ah, bh[3][0], bh[3][1]);
                MMA_F16(acc[mf][0], al, bh[0][0], bh[0][1]);
                MMA_F16(acc[mf][1], al, bh[1][0], bh[1][1]);
                MMA_F16(acc[mf][2], al, bh[2][0], bh[2][1]);
                MMA_F16(acc[mf][3], al, bh[3][0], bh[3][1]);
            }
        }
        __syncthreads();
    }

    // epilogue
#pragma unroll
    for (int mf = 0; mf < 4; ++mf) {
        int r = row0 + wy * 64 + mf * 16 + (lane >> 2);
#pragma unroll
        for (int nf = 0; nf < 4; ++nf) {
            int col = col0 + wx * 32 + nf * 8 + ((lane & 3) << 1);
            float b0 = bias[col], b1 = bias[col + 1];
            float v0 = (acc[mf][nf][0] + b0) * alpha;
            float v1 = (acc[mf][nf][1] + b1) * alpha;
            float v2 = (acc[mf][nf][2] + b0) * alpha;
            float v3 = (acc[mf][nf][3] + b1) * alpha;
            if (MODE == 0) {
                *(float2*)(Cf + (size_t)r * E_DIM + col)       = make_float2(v0, v1);
                *(float2*)(Cf + (size_t)(r + 8) * E_DIM + col) = make_float2(v2, v3);
            } else {
                *(uint32_t*)(Ch + (size_t)r * E_DIM + col)       = pack_h2(v0, v1);
                *(uint32_t*)(Ch + (size_t)(r + 8) * E_DIM + col) = pack_h2(v2, v3);
            }
        }
    }
}

__global__ void __launch_bounds__(256, 2)
qkv_kernel(const float* __restrict__ bq, const float* __restrict__ bk,
           const float* __restrict__ bv)
{
    const int z = blockIdx.z;
    const __half* Bh = gW + ((size_t)z << 20);
    if (z == 0)      gemm_cp<1>(gXh, gXl, Bh, bq, 0.125f, nullptr, gQ);
    else if (z == 1) gemm_cp<1>(gXh, gXl, Bh, bk, 1.0f,   nullptr, gK);
    else             gemm_cp<1>(gXh, gXl, Bh, bv, 1.0f,   nullptr, gV);
}

__global__ void __launch_bounds__(256, 2)
oproj_kernel(const float* __restrict__ bo, float* __restrict__ out)
{
    gemm_cp<0>(gAh, gAl, gW + ((size_t)3 << 20), bo, 1.0f, out, nullptr);
}

// ===========================================================================
// Flash attention (causal), single-fp16 Q/K/V. S = 1 MMA term, PV = 1 term
// with P rounded to fp16 and l computed from the ROUNDED P (consistent).
// BR=128 (8 warps x m16), BC=64. Double-buffered K/V; balanced q-tile pairs.
// ===========================================================================
#define FPITCH 72
#define FQ_E   (128 * FPITCH)              // 9216
#define FKV_E  (64 * FPITCH)               // 4608 per array
#define FSTAGE_E (2 * FKV_E)               // K + V per stage
#define FKV0_E FQ_E
#define FSMEM_BYTES ((FKV0_E + 2 * FSTAGE_E) * 2)   // 55296

__device__ __forceinline__ void flash_kv_produce(uint32_t smb, int stage, int j0,
                                                 int b, int colbase, int tid)
{
#pragma unroll
    for (int i = 0; i < 4; ++i) {
        int id  = tid + i * 256;          // 0..1023
        int arr = id >> 9;                // 0:K 1:V
        int rid = (id >> 3) & 63;
        int cc  = id & 7;
        const __half* g = arr ? gV : gK;
        const __half* src = g + ((size_t)(j0 + rid) * B_DIM + b) * E_DIM + colbase + cc * 8;
        uint32_t dst = smb + (uint32_t)(FKV0_E + stage * FSTAGE_E + arr * FKV_E + rid * FPITCH + cc * 8) * 2;
        CP_ASYNC16(dst, src);
    }
}

__device__ __forceinline__ void flash_one(int qt, uint32_t smb, int b, int colbase,
                                          int tid, int lane, int w,
                                          int qOffE, int kOffE, int vOffE)
{
    const int i0 = qt * 128;
    const int ktmax = 2 * qt + 1;

    // prologue: Q tile + KV stage 0 in one cp.async group
#pragma unroll
    for (int i = 0; i < 4; ++i) {
        int id  = tid + i * 256;          // 0..1023
        int rid = id >> 3;
        int cc  = id & 7;
        const __half* src = gQ + ((size_t)(i0 + rid) * B_DIM + b) * E_DIM + colbase + cc * 8;
        uint32_t dst = smb + (uint32_t)(rid * FPITCH + cc * 8) * 2;
        CP_ASYNC16(dst, src);
    }
    flash_kv_produce(smb, 0, 0, b, colbase, tid);
    CP_COMMIT();

    float s_m[2] = {-1e9f, -1e9f};
    float s_l[2] = {0.f, 0.f};
    float o[8][4];
#pragma unroll
    for (int i = 0; i < 8; i++)
#pragma unroll
        for (int j = 0; j < 4; j++) o[i][j] = 0.f;

    const int rg0 = i0 + w * 16 + (lane >> 2);
    const uint32_t qB = smb;

    for (int kt = 0; kt <= ktmax; ++kt) {
        CP_WAIT(0);
        __syncthreads();
        if (kt + 1 <= ktmax) {
            flash_kv_produce(smb, (kt + 1) & 1, (kt + 1) * 64, b, colbase, tid);
            CP_COMMIT();
        }

        const int j0 = kt * 64;
        const uint32_t stKV = smb + (uint32_t)(FKV0_E + (kt & 1) * FSTAGE_E) * 2;
        const uint32_t kB = stKV;
        const uint32_t vB = stKV + FKV_E * 2;

        // ---- S = Q @ K^T (single term) ----
        float s[8][4];
#pragma unroll
        for (int i = 0; i < 8; i++)
#pragma unroll
            for (int j = 0; j < 4; j++) s[i][j] = 0.f;

#pragma unroll
        for (int kb = 0; kb < 4; ++kb) {
            uint32_t a[4];
            LDSM4(a[0], a[1], a[2], a[3], qB + (qOffE + kb * 16) * 2);
            uint32_t kh[4][4];
#pragma unroll
            for (int np = 0; np < 4; ++np) {
                int boe = kOffE + np * 16 * FPITCH + kb * 16;
                LDSM4(kh[np][0], kh[np][1], kh[np][2], kh[np][3], kB + boe * 2);
            }
#pragma unroll
            for (int np = 0; np < 4; ++np) {
                MMA_F16(s[2 * np],     a, kh[np][0], kh[np][1]);
                MMA_F16(s[2 * np + 1], a, kh[np][2], kh[np][3]);
            }
        }

        // ---- causal mask ----
        if (j0 + 63 > i0 + w * 16) {
#pragma unroll
            for (int nf = 0; nf < 8; ++nf) {
                int j = j0 + nf * 8 + ((lane & 3) << 1);
                if (j     > rg0)     s[nf][0] = -1e9f;
                if (j + 1 > rg0)     s[nf][1] = -1e9f;
                if (j     > rg0 + 8) s[nf][2] = -1e9f;
                if (j + 1 > rg0 + 8) s[nf][3] = -1e9f;
            }
        }

        // ---- online softmax; P rounded to fp16, l from rounded P ----
#pragma unroll
        for (int half = 0; half < 2; ++half) {
            const int e0 = half * 2, e1 = half * 2 + 1;
            float vmax = -1e9f;
#pragma unroll
            for (int nf = 0; nf < 8; ++nf)
                vmax = fmaxf(vmax, fmaxf(s[nf][e0], s[nf][e1]));
            vmax = fmaxf(vmax, __shfl_xor_sync(0xffffffffu, vmax, 1));
            vmax = fmaxf(vmax, __shfl_xor_sync(0xffffffffu, vmax, 2));
            float mnew = fmaxf(s_m[half], vmax);
            float corr = fast_exp(s_m[half] - mnew);
            float rsum = 0.f;
#pragma unroll
            for (int nf = 0; nf < 8; ++nf) {
                float p0 = __half2float(__float2half_rn(fast_exp(s[nf][e0] - mnew)));
                float p1 = __half2float(__float2half_rn(fast_exp(s[nf][e1] - mnew)));
                s[nf][e0] = p0; s[nf][e1] = p1;
                rsum += p0 + p1;
            }
            rsum += __shfl_xor_sync(0xffffffffu, rsum, 1);
            rsum += __shfl_xor_sync(0xffffffffu, rsum, 2);
            s_l[half] = s_l[half] * corr + rsum;
            s_m[half] = mnew;
#pragma unroll
            for (int nf = 0; nf < 8; ++nf) {
                o[nf][e0] *= corr;
                o[nf][e1] *= corr;
            }
        }

        // ---- O += P @ V (single term) ----
#pragma unroll
        for (int kc = 0; kc < 4; ++kc) {
            uint32_t ph[4];
            ph[0] = pack_h2(s[2 * kc][0],     s[2 * kc][1]);
            ph[1] = pack_h2(s[2 * kc][2],     s[2 * kc][3]);
            ph[2] = pack_h2(s[2 * kc + 1][0], s[2 * kc + 1][1]);
            ph[3] = pack_h2(s[2 * kc + 1][2], s[2 * kc + 1][3]);
            uint32_t wh[4][4];
#pragma unroll
            for (int np = 0; np < 4; ++np) {
                int voe = vOffE + kc * 16 * FPITCH + np * 16;
                LDSM4T(wh[np][0], wh[np][1], wh[np][2], wh[np][3], vB + voe * 2);
            }
#pragma unroll
            for (int np = 0; np < 4; ++np) {
                MMA_F16(o[2 * np],     ph, wh[np][0], wh[np][1]);
                MMA_F16(o[2 * np + 1], ph, wh[np][2], wh[np][3]);
            }
        }
    }
    __syncthreads();   // smem reads done before caller refills Q region

    // ---- finalize: attn = o / l, stored as fp16 hi/lo split ----
    const float inv0 = 1.f / s_l[0];
    const float inv1 = 1.f / s_l[1];
#pragma unroll
    for (int nf = 0; nf < 8; ++nf) {
        int col = colbase + nf * 8 + ((lane & 3) << 1);
        float v0 = o[nf][0] * inv0, v1 = o[nf][1] * inv0;
        float v2 = o[nf][2] * inv1, v3 = o[nf][3] * inv1;
        __half h0, h1, h2, h3, l0, l1, l2, l3;
        split_h(v0, h0, l0); split_h(v1, h1, l1);
        split_h(v2, h2, l2); split_h(v3, h3, l3);
        size_t r0off = ((size_t)rg0 * B_DIM + b) * E_DIM + col;
        size_t r1off = ((size_t)(rg0 + 8) * B_DIM + b) * E_DIM + col;
        __half2 t;
        t.x = h0; t.y = h1; *(uint32_t*)(gAh + r0off) = *(uint32_t*)&t;
        t.x = l0; t.y = l1; *(uint32_t*)(gAl + r0off) = *(uint32_t*)&t;
        t.x = h2; t.y = h3; *(uint32_t*)(gAh + r1off) = *(uint32_t*)&t;
        t.x = l2; t.y = l3; *(uint32_t*)(gAl + r1off) = *(uint32_t*)&t;
    }
}

__global__ void __launch_bounds__(256)
flash_mma_kernel()
{
    extern __shared__ char dynsm[];
    const uint32_t smb = smem_u32(dynsm);

    const int tid  = threadIdx.x;
    const int lane = tid & 31;
    const int w    = tid >> 5;
    const int pair = blockIdx.x;          // 0..7
    const int head = blockIdx.y;          // 0..31
    const int b    = head >> 4;
    const int h    = head & 15;
    const int colbase = h * DH;

    const int qOffE = (w * 16 + (lane & 15)) * FPITCH + ((lane >> 4) & 1) * 8;
    const int kOffE = ((lane & 7) + ((lane >> 4) & 1) * 8) * FPITCH + ((lane >> 3) & 1) * 8;
    const int vOffE = ((lane & 7) + ((lane >> 3) & 1) * 8) * FPITCH + ((lane >> 4) & 1) * 8;

    flash_one(pair,      smb, b, colbase, tid, lane, w, qOffE, kOffE, vOffE);
    flash_one(15 - pair, smb, b, colbase, tid, lane, w, qOffE, kOffE, vOffE);
}

// ===========================================================================
// kernel_launch
// Inputs: query, Wq, bq, Wk, bk, Wv, bv, Wo, bo, attn_mask (ignored: causal)
// ===========================================================================
extern "C" void kernel_launch(void* const* d_in, const int* in_sizes, int n_in,
                              void* d_out, int out_size)
{
    const float* query = (const float*)d_in[0];
    const float* Wq    = (const float*)d_in[1];
    const float* bq    = (const float*)d_in[2];
    const float* Wk    = (const float*)d_in[3];
    const float* bk    = (const float*)d_in[4];
    const float* Wv    = (const float*)d_in[5];
    const float* bv    = (const float*)d_in[6];
    const float* Wo    = (const float*)d_in[7];
    const float* bo    = (const float*)d_in[8];
    float* out = (float*)d_out;

    cudaFuncSetAttribute(qkv_kernel, cudaFuncAttributeMaxDynamicSharedMemorySize, GSMEM_BYTES);
    cudaFuncSetAttribute(oproj_kernel, cudaFuncAttributeMaxDynamicSharedMemorySize, GSMEM_BYTES);
    cudaFuncSetAttribute(flash_mma_kernel, cudaFuncAttributeMaxDynamicSharedMemorySize, FSMEM_BYTES);

    // split X to fp16 hi/lo; weights to fp16 hi
    convert_kernel<<<8192, 256>>>(query, Wq, Wk, Wv, Wo);

    // QKV projections -> single fp16 q,k,v
    qkv_kernel<<<dim3(E_DIM / 128, MROWS / 128, 3), 256, GSMEM_BYTES>>>(bq, bk, bv);

    // causal flash attention: 8 balanced q-tile pairs x 32 heads
    flash_mma_kernel<<<dim3(8, B_DIM * H_DIM), 256, FSMEM_BYTES>>>();

    // output projection (attn hi/lo) -> f32 out
    oproj_kernel<<<dim3(E_DIM / 128, MROWS / 128), 256, GSMEM_BYTES>>>(bo, out);
}

// round 9
// speedup vs baseline: 1.9871x; 1.2607x over previous
#include <cuda_runtime.h>
#include <cuda_fp16.h>
#include <math.h>
#include <stdint.h>

// Problem constants
#define T_DIM 2048
#define B_DIM 2
#define E_DIM 1024
#define H_DIM 16
#define DH    64
#define MROWS (T_DIM * B_DIM)   // 4096
#define NELEM (MROWS * E_DIM)   // 4194304

// Scratch (device globals — no allocation allowed). All fp16.
__device__ __half gXh[NELEM], gXl[NELEM];   // input X split hi/lo
__device__ __half gW[NELEM];                // Wq,Wk,Wv,Wo hi only (1M each)
__device__ __half gQ[NELEM], gK[NELEM], gV[NELEM];   // single fp16
__device__ __half gA[NELEM];                // attn output, single fp16

// ===========================================================================
// Helpers
// ===========================================================================
__device__ __forceinline__ uint32_t smem_u32(const void* p) {
    uint32_t a;
    asm("{ .reg .u64 t; cvta.to.shared.u64 t, %1; cvt.u32.u64 %0, t; }" : "=r"(a) : "l"(p));
    return a;
}

#define LDSM4(R0, R1, R2, R3, ADDR) \
    asm volatile("ldmatrix.sync.aligned.m8n8.x4.shared.b16 {%0,%1,%2,%3}, [%4];" \
                 : "=r"(R0), "=r"(R1), "=r"(R2), "=r"(R3) : "r"(ADDR))

#define LDSM4T(R0, R1, R2, R3, ADDR) \
    asm volatile("ldmatrix.sync.aligned.m8n8.x4.trans.shared.b16 {%0,%1,%2,%3}, [%4];" \
                 : "=r"(R0), "=r"(R1), "=r"(R2), "=r"(R3) : "r"(ADDR))

#define MMA_F16(D, A, B0, B1) \
    asm volatile("mma.sync.aligned.m16n8k16.row.col.f32.f16.f16.f32 " \
                 "{%0,%1,%2,%3}, {%4,%5,%6,%7}, {%8,%9}, {%0,%1,%2,%3};" \
                 : "+f"((D)[0]), "+f"((D)[1]), "+f"((D)[2]), "+f"((D)[3]) \
                 : "r"((A)[0]), "r"((A)[1]), "r"((A)[2]), "r"((A)[3]), "r"(B0), "r"(B1))

#define CP_ASYNC16(DST, SRC) \
    asm volatile("cp.async.cg.shared.global [%0], [%1], 16;" :: "r"(DST), "l"(SRC) : "memory")
#define CP_COMMIT() asm volatile("cp.async.commit_group;" ::: "memory")
#define CP_WAIT(N)  asm volatile("cp.async.wait_group %0;" :: "n"(N) : "memory")

__device__ __forceinline__ uint32_t pack_h2(float a, float b) {
    __half2 h;
    h.x = __float2half_rn(a); h.y = __float2half_rn(b);
    return *(uint32_t*)&h;
}

// split fp32 into fp16 hi + fp16 residual lo
__device__ __forceinline__ void split_h(float a, __half& hi, __half& lo) {
    hi = __float2half_rn(a);
    lo = __float2half_rn(a - __half2float(hi));
}

// fast exp on FMA pipe (no MUFU)
__device__ __forceinline__ float fast_exp(float x) {
    float y = fmaxf(x * 1.44269504f, -126.0f);
    int   e = __float2int_rn(y);
    float f = y - (float)e;
    float p = 1.33336e-3f;
    p = fmaf(p, f, 9.61812e-3f);
    p = fmaf(p, f, 5.55041e-2f);
    p = fmaf(p, f, 2.402265e-1f);
    p = fmaf(p, f, 6.931472e-1f);
    p = fmaf(p, f, 1.0f);
    return __int_as_float((e + 127) << 23) * p;
}

// ===========================================================================
// Convert: X -> fp16 hi/lo split; W's -> fp16 hi only.
// ===========================================================================
__global__ void __launch_bounds__(256)
convert_kernel(const float* __restrict__ X,
               const float* __restrict__ Wq, const float* __restrict__ Wk,
               const float* __restrict__ Wv, const float* __restrict__ Wo)
{
    int i = blockIdx.x * 256 + threadIdx.x;       // 0 .. 2097151
    if (i < 1048576) {
        float4 v = ((const float4*)X)[i];
        __half h0, h1, h2, h3, l0, l1, l2, l3;
        split_h(v.x, h0, l0); split_h(v.y, h1, l1);
        split_h(v.z, h2, l2); split_h(v.w, h3, l3);
        __half2 H01; H01.x = h0; H01.y = h1;
        __half2 H23; H23.x = h2; H23.y = h3;
        __half2 L01; L01.x = l0; L01.y = l1;
        __half2 L23; L23.x = l2; L23.y = l3;
        *(uint2*)(gXh + (size_t)i * 4) = make_uint2(*(uint32_t*)&H01, *(uint32_t*)&H23);
        *(uint2*)(gXl + (size_t)i * 4) = make_uint2(*(uint32_t*)&L01, *(uint32_t*)&L23);
    } else {
        int j = i - 1048576;
        int r = j >> 18;                           // 0..3 -> Wq,Wk,Wv,Wo
        int off = j & 0x3FFFF;
        const float4* src = (const float4*)(r == 0 ? Wq : r == 1 ? Wk : r == 2 ? Wv : Wo);
        float4 v = src[off];
        __half2 H01, H23;
        H01.x = __float2half_rn(v.x); H01.y = __float2half_rn(v.y);
        H23.x = __float2half_rn(v.z); H23.y = __float2half_rn(v.w);
        *(uint2*)(gW + ((size_t)r << 20) + (size_t)off * 4) =
            make_uint2(*(uint32_t*)&H01, *(uint32_t*)&H23);
    }
}

// ===========================================================================
// GEMM: C = (A @ Wh^T + bias) * alpha with NT A-terms (1 or 2 fp16 MMAs/frag)
// CTA 128x128, 8 warps (2x4), warp 64x32, BK=32, 2-stage cp.async, 2 CTAs/SM.
// Stage layout: [A0, (A1), B] arrays of 128x40 fp16.
// MODE 0: f32 out.  MODE 1: single-fp16 out.
// ===========================================================================
#define GPITCH 40
#define GARR_E (128 * GPITCH)              // 5120 elems per array
#define GSMEM2 (2 * 3 * GARR_E * 2)        // 61440 (NT=2)
#define GSMEM1 (2 * 2 * GARR_E * 2)        // 40960 (NT=1)

template <int NT>
__device__ __forceinline__ void gemm_produce(
    uint32_t smb, int stage,
    const __half* __restrict__ A0, const __half* __restrict__ A1,
    const __half* __restrict__ Bh,
    int row0, int col0, int k0, int tid)
{
    const int STAGE_E = (NT + 1) * GARR_E;
#pragma unroll
    for (int i = 0; i < (NT + 1) * 2; ++i) {
        int id  = tid + i * 256;          // 0 .. (NT+1)*512-1
        int arr = id >> 9;                // 0..NT-1 = A terms, NT = B
        int rid = (id >> 2) & 127;
        int cc  = id & 3;
        const __half* g = (arr < NT) ? (arr == 0 ? A0 : A1) : Bh;
        int grow = ((arr < NT) ? row0 : col0) + rid;
        const __half* src = g + (size_t)grow * E_DIM + k0 + cc * 8;
        uint32_t dst = smb + (uint32_t)(stage * STAGE_E + arr * GARR_E + rid * GPITCH + cc * 8) * 2;
        CP_ASYNC16(dst, src);
    }
}

template <int NT, int MODE>
__device__ __forceinline__ void gemm_cp(
    const __half* __restrict__ A0, const __half* __restrict__ A1,
    const __half* __restrict__ Bh,
    const float* __restrict__ bias, float alpha,
    float* __restrict__ Cf, __half* __restrict__ Ch)
{
    extern __shared__ char dynsm[];
    const uint32_t smb = smem_u32(dynsm);
    const int STAGE_E = (NT + 1) * GARR_E;
    const int tid  = threadIdx.x;
    const int lane = tid & 31;
    const int wid  = tid >> 5;
    const int wy   = wid >> 2;           // 0..1
    const int wx   = wid & 3;            // 0..3
    const int row0 = blockIdx.y * 128;
    const int col0 = blockIdx.x * 128;

    const int aOffE = (wy * 64 + (lane & 15)) * GPITCH + ((lane >> 4) & 1) * 8;
    const int bOffE = (wx * 32 + (lane & 7) + ((lane >> 4) & 1) * 8) * GPITCH + ((lane >> 3) & 1) * 8;

    float acc[4][4][4];
#pragma unroll
    for (int i = 0; i < 4; i++)
#pragma unroll
        for (int j = 0; j < 4; j++)
#pragma unroll
            for (int k = 0; k < 4; k++) acc[i][j][k] = 0.f;

    gemm_produce<NT>(smb, 0, A0, A1, Bh, row0, col0, 0, tid);
    CP_COMMIT();

    for (int c = 0; c < 32; ++c) {
        CP_WAIT(0);
        __syncthreads();
        if (c + 1 < 32) {
            gemm_produce<NT>(smb, (c + 1) & 1, A0, A1, Bh, row0, col0, (c + 1) * 32, tid);
            CP_COMMIT();
        }

        const uint32_t stA = smb + (uint32_t)((c & 1) * STAGE_E) * 2;
        const uint32_t aHb = stA;
        const uint32_t aLb = stA + GARR_E * 2;            // valid when NT==2
        const uint32_t bHb = stA + NT * GARR_E * 2;

#pragma unroll
        for (int kb = 0; kb < 2; ++kb) {
            uint32_t bh[4][2];
#pragma unroll
            for (int np = 0; np < 2; ++np) {
                int boe = bOffE + np * 16 * GPITCH + kb * 16;
                LDSM4(bh[2 * np][0], bh[2 * np][1], bh[2 * np + 1][0], bh[2 * np + 1][1],
                      bHb + boe * 2);
            }
#pragma unroll
            for (int mf = 0; mf < 4; ++mf) {
                int aoe = aOffE + mf * 16 * GPITCH + kb * 16;
                uint32_t ah[4];
                LDSM4(ah[0], ah[1], ah[2], ah[3], aHb + aoe * 2);
                if (NT == 2) {
                    uint32_t al[4];
                    LDSM4(al[0], al[1], al[2], al[3], aLb + aoe * 2);
                    MMA_F16(acc[mf][0], ah, bh[0][0], bh[0][1]);
                    MMA_F16(acc[mf][1], ah, bh[1][0], bh[1][1]);
                    MMA_F16(acc[mf][2], ah, bh[2][0], bh[2][1]);
                    MMA_F16(acc[mf][3], ah, bh[3][0], bh[3][1]);
                    MMA_F16(acc[mf][0], al, bh[0][0], bh[0][1]);
                    MMA_F16(acc[mf][1], al, bh[1][0], bh[1][1]);
                    MMA_F16(acc[mf][2], al, bh[2][0], bh[2][1]);
                    MMA_F16(acc[mf][3], al, bh[3][0], bh[3][1]);
                } else {
                    MMA_F16(acc[mf][0], ah, bh[0][0], bh[0][1]);
                    MMA_F16(acc[mf][1], ah, bh[1][0], bh[1][1]);
                    MMA_F16(acc[mf][2], ah, bh[2][0], bh[2][1]);
                    MMA_F16(acc[mf][3], ah, bh[3][0], bh[3][1]);
                }
            }
        }
        __syncthreads();
    }

    // epilogue
#pragma unroll
    for (int mf = 0; mf < 4; ++mf) {
        int r = row0 + wy * 64 + mf * 16 + (lane >> 2);
#pragma unroll
        for (int nf = 0; nf < 4; ++nf) {
            int col = col0 + wx * 32 + nf * 8 + ((lane & 3) << 1);
            float b0 = bias[col], b1 = bias[col + 1];
            float v0 = (acc[mf][nf][0] + b0) * alpha;
            float v1 = (acc[mf][nf][1] + b1) * alpha;
            float v2 = (acc[mf][nf][2] + b0) * alpha;
            float v3 = (acc[mf][nf][3] + b1) * alpha;
            if (MODE == 0) {
                *(float2*)(Cf + (size_t)r * E_DIM + col)       = make_float2(v0, v1);
                *(float2*)(Cf + (size_t)(r + 8) * E_DIM + col) = make_float2(v2, v3);
            } else {
                *(uint32_t*)(Ch + (size_t)r * E_DIM + col)       = pack_h2(v0, v1);
                *(uint32_t*)(Ch + (size_t)(r + 8) * E_DIM + col) = pack_h2(v2, v3);
            }
        }
    }
}

__global__ void __launch_bounds__(256, 2)
qkv_kernel(const float* __restrict__ bq, const float* __restrict__ bk,
           const float* __restrict__ bv)
{
    const int z = blockIdx.z;
    const __half* Bh = gW + ((size_t)z << 20);
    // Q,K: 1-term (softmax absorbs X-rounding); V: 2-term (error flows through)
    if (z == 0)      gemm_cp<1, 1>(gXh, nullptr, Bh, bq, 0.125f, nullptr, gQ);
    else if (z == 1) gemm_cp<1, 1>(gXh, nullptr, Bh, bk, 1.0f,   nullptr, gK);
    else             gemm_cp<2, 1>(gXh, gXl,     Bh, bv, 1.0f,   nullptr, gV);
}

__global__ void __launch_bounds__(256, 2)
oproj_kernel(const float* __restrict__ bo, float* __restrict__ out)
{
    gemm_cp<1, 0>(gA, nullptr, gW + ((size_t)3 << 20), bo, 1.0f, out, nullptr);
}

// ===========================================================================
// Flash attention (causal), single-fp16 Q/K/V. S = 1 MMA term, PV = 1 term
// with P rounded to fp16 and l computed from the ROUNDED P (consistent).
// BR=128 (8 warps x m16), BC=64. Double-buffered K/V; balanced q-tile pairs.
// ===========================================================================
#define FPITCH 72
#define FQ_E   (128 * FPITCH)              // 9216
#define FKV_E  (64 * FPITCH)               // 4608 per array
#define FSTAGE_E (2 * FKV_E)               // K + V per stage
#define FKV0_E FQ_E
#define FSMEM_BYTES ((FKV0_E + 2 * FSTAGE_E) * 2)   // 55296

__device__ __forceinline__ void flash_kv_produce(uint32_t smb, int stage, int j0,
                                                 int b, int colbase, int tid)
{
#pragma unroll
    for (int i = 0; i < 4; ++i) {
        int id  = tid + i * 256;          // 0..1023
        int arr = id >> 9;                // 0:K 1:V
        int rid = (id >> 3) & 63;
        int cc  = id & 7;
        const __half* g = arr ? gV : gK;
        const __half* src = g + ((size_t)(j0 + rid) * B_DIM + b) * E_DIM + colbase + cc * 8;
        uint32_t dst = smb + (uint32_t)(FKV0_E + stage * FSTAGE_E + arr * FKV_E + rid * FPITCH + cc * 8) * 2;
        CP_ASYNC16(dst, src);
    }
}

__device__ __forceinline__ void flash_one(int qt, uint32_t smb, int b, int colbase,
                                          int tid, int lane, int w,
                                          int qOffE, int kOffE, int vOffE)
{
    const int i0 = qt * 128;
    const int ktmax = 2 * qt + 1;

    // prologue: Q tile + KV stage 0 in one cp.async group
#pragma unroll
    for (int i = 0; i < 4; ++i) {
        int id  = tid + i * 256;          // 0..1023
        int rid = id >> 3;
        int cc  = id & 7;
        const __half* src = gQ + ((size_t)(i0 + rid) * B_DIM + b) * E_DIM + colbase + cc * 8;
        uint32_t dst = smb + (uint32_t)(rid * FPITCH + cc * 8) * 2;
        CP_ASYNC16(dst, src);
    }
    flash_kv_produce(smb, 0, 0, b, colbase, tid);
    CP_COMMIT();

    float s_m[2] = {-1e9f, -1e9f};
    float s_l[2] = {0.f, 0.f};
    float o[8][4];
#pragma unroll
    for (int i = 0; i < 8; i++)
#pragma unroll
        for (int j = 0; j < 4; j++) o[i][j] = 0.f;

    const int rg0 = i0 + w * 16 + (lane >> 2);
    const uint32_t qB = smb;

    for (int kt = 0; kt <= ktmax; ++kt) {
        CP_WAIT(0);
        __syncthreads();
        if (kt + 1 <= ktmax) {
            flash_kv_produce(smb, (kt + 1) & 1, (kt + 1) * 64, b, colbase, tid);
            CP_COMMIT();
        }

        const int j0 = kt * 64;
        const uint32_t stKV = smb + (uint32_t)(FKV0_E + (kt & 1) * FSTAGE_E) * 2;
        const uint32_t kB = stKV;
        const uint32_t vB = stKV + FKV_E * 2;

        // ---- S = Q @ K^T (single term) ----
        float s[8][4];
#pragma unroll
        for (int i = 0; i < 8; i++)
#pragma unroll
            for (int j = 0; j < 4; j++) s[i][j] = 0.f;

#pragma unroll
        for (int kb = 0; kb < 4; ++kb) {
            uint32_t a[4];
            LDSM4(a[0], a[1], a[2], a[3], qB + (qOffE + kb * 16) * 2);
            uint32_t kh[4][4];
#pragma unroll
            for (int np = 0; np < 4; ++np) {
                int boe = kOffE + np * 16 * FPITCH + kb * 16;
                LDSM4(kh[np][0], kh[np][1], kh[np][2], kh[np][3], kB + boe * 2);
            }
#pragma unroll
            for (int np = 0; np < 4; ++np) {
                MMA_F16(s[2 * np],     a, kh[np][0], kh[np][1]);
                MMA_F16(s[2 * np + 1], a, kh[np][2], kh[np][3]);
            }
        }

        // ---- causal mask ----
        if (j0 + 63 > i0 + w * 16) {
#pragma unroll
            for (int nf = 0; nf < 8; ++nf) {
                int j = j0 + nf * 8 + ((lane & 3) << 1);
                if (j     > rg0)     s[nf][0] = -1e9f;
                if (j + 1 > rg0)     s[nf][1] = -1e9f;
                if (j     > rg0 + 8) s[nf][2] = -1e9f;
                if (j + 1 > rg0 + 8) s[nf][3] = -1e9f;
            }
        }

        // ---- online softmax; P rounded to fp16, l from rounded P ----
#pragma unroll
        for (int half = 0; half < 2; ++half) {
            const int e0 = half * 2, e1 = half * 2 + 1;
            float vmax = -1e9f;
#pragma unroll
            for (int nf = 0; nf < 8; ++nf)
                vmax = fmaxf(vmax, fmaxf(s[nf][e0], s[nf][e1]));
            vmax = fmaxf(vmax, __shfl_xor_sync(0xffffffffu, vmax, 1));
            vmax = fmaxf(vmax, __shfl_xor_sync(0xffffffffu, vmax, 2));
            float mnew = fmaxf(s_m[half], vmax);
            float corr = fast_exp(s_m[half] - mnew);
            float rsum = 0.f;
#pragma unroll
            for (int nf = 0; nf < 8; ++nf) {
                float p0 = __half2float(__float2half_rn(fast_exp(s[nf][e0] - mnew)));
                float p1 = __half2float(__float2half_rn(fast_exp(s[nf][e1] - mnew)));
                s[nf][e0] = p0; s[nf][e1] = p1;
                rsum += p0 + p1;
            }
            rsum += __shfl_xor_sync(0xffffffffu, rsum, 1);
            rsum += __shfl_xor_sync(0xffffffffu, rsum, 2);
            s_l[half] = s_l[half] * corr + rsum;
            s_m[half] = mnew;
#pragma unroll
            for (int nf = 0; nf < 8; ++nf) {
                o[nf][e0] *= corr;
                o[nf][e1] *= corr;
            }
        }

        // ---- O += P @ V (single term) ----
#pragma unroll
        for (int kc = 0; kc < 4; ++kc) {
            uint32_t ph[4];
            ph[0] = pack_h2(s[2 * kc][0],     s[2 * kc][1]);
            ph[1] = pack_h2(s[2 * kc][2],     s[2 * kc][3]);
            ph[2] = pack_h2(s[2 * kc + 1][0], s[2 * kc + 1][1]);
            ph[3] = pack_h2(s[2 * kc + 1][2], s[2 * kc + 1][3]);
            uint32_t wh[4][4];
#pragma unroll
            for (int np = 0; np < 4; ++np) {
                int voe = vOffE + kc * 16 * FPITCH + np * 16;
                LDSM4T(wh[np][0], wh[np][1], wh[np][2], wh[np][3], vB + voe * 2);
            }
#pragma unroll
            for (int np = 0; np < 4; ++np) {
                MMA_F16(o[2 * np],     ph, wh[np][0], wh[np][1]);
                MMA_F16(o[2 * np + 1], ph, wh[np][2], wh[np][3]);
            }
        }
    }
    __syncthreads();   // smem reads done before caller refills Q region

    // ---- finalize: attn = o / l, stored as single fp16 ----
    const float inv0 = 1.f / s_l[0];
    const float inv1 = 1.f / s_l[1];
#pragma unroll
    for (int nf = 0; nf < 8; ++nf) {
        int col = colbase + nf * 8 + ((lane & 3) << 1);
        size_t r0off = ((size_t)rg0 * B_DIM + b) * E_DIM + col;
        size_t r1off = ((size_t)(rg0 + 8) * B_DIM + b) * E_DIM + col;
        *(uint32_t*)(gA + r0off) = pack_h2(o[nf][0] * inv0, o[nf][1] * inv0);
        *(uint32_t*)(gA + r1off) = pack_h2(o[nf][2] * inv1, o[nf][3] * inv1);
    }
}

__global__ void __launch_bounds__(256)
flash_mma_kernel()
{
    extern __shared__ char dynsm[];
    const uint32_t smb = smem_u32(dynsm);

    const int tid  = threadIdx.x;
    const int lane = tid & 31;
    const int w    = tid >> 5;
    const int pair = blockIdx.x;          // 0..7
    const int head = blockIdx.y;          // 0..31
    const int b    = head >> 4;
    const int h    = head & 15;
    const int colbase = h * DH;

    const int qOffE = (w * 16 + (lane & 15)) * FPITCH + ((lane >> 4) & 1) * 8;
    const int kOffE = ((lane & 7) + ((lane >> 4) & 1) * 8) * FPITCH + ((lane >> 3) & 1) * 8;
    const int vOffE = ((lane & 7) + ((lane >> 3) & 1) * 8) * FPITCH + ((lane >> 4) & 1) * 8;

    flash_one(pair,      smb, b, colbase, tid, lane, w, qOffE, kOffE, vOffE);
    flash_one(15 - pair, smb, b, colbase, tid, lane, w, qOffE, kOffE, vOffE);
}

// ===========================================================================
// kernel_launch
// Inputs: query, Wq, bq, Wk, bk, Wv, bv, Wo, bo, attn_mask (ignored: causal)
// ===========================================================================
extern "C" void kernel_launch(void* const* d_in, const int* in_sizes, int n_in,
                              void* d_out, int out_size)
{
    const float* query = (const float*)d_in[0];
    const float* Wq    = (const float*)d_in[1];
    const float* bq    = (const float*)d_in[2];
    const float* Wk    = (const float*)d_in[3];
    const float* bk    = (const float*)d_in[4];
    const float* Wv    = (const float*)d_in[5];
    const float* bv    = (const float*)d_in[6];
    const float* Wo    = (const float*)d_in[7];
    const float* bo    = (const float*)d_in[8];
    float* out = (float*)d_out;

    cudaFuncSetAttribute(qkv_kernel, cudaFuncAttributeMaxDynamicSharedMemorySize, GSMEM2);
    cudaFuncSetAttribute(oproj_kernel, cudaFuncAttributeMaxDynamicSharedMemorySize, GSMEM1);
    cudaFuncSetAttribute(flash_mma_kernel, cudaFuncAttributeMaxDynamicSharedMemorySize, FSMEM_BYTES);

    // split X to fp16 hi/lo; weights to fp16 hi
    convert_kernel<<<8192, 256>>>(query, Wq, Wk, Wv, Wo);

    // QKV projections: Q,K 1-term; V 2-term -> single fp16 q,k,v
    qkv_kernel<<<dim3(E_DIM / 128, MROWS / 128, 3), 256, GSMEM2>>>(bq, bk, bv);

    // causal flash attention: 8 balanced q-tile pairs x 32 heads
    flash_mma_kernel<<<dim3(8, B_DIM * H_DIM), 256, FSMEM_BYTES>>>();

    // output projection (single-term) -> f32 out
    oproj_kernel<<<dim3(E_DIM / 128, MROWS / 128), 256, GSMEM1>>>(bo, out);
}

// round 10
// speedup vs baseline: 2.3030x; 1.1589x over previous
#include <cuda_runtime.h>
#include <cuda_fp16.h>
#include <math.h>
#include <stdint.h>

// Problem constants
#define T_DIM 2048
#define B_DIM 2
#define E_DIM 1024
#define H_DIM 16
#define DH    64
#define MROWS (T_DIM * B_DIM)   // 4096
#define NELEM (MROWS * E_DIM)   // 4194304

// Scratch (device globals — no allocation allowed). All fp16.
__device__ __half gX[NELEM];                // input X, fp16
__device__ __half gW[NELEM];                // Wq,Wk,Wv,Wo fp16 (1M each)
__device__ __half gQ[NELEM], gK[NELEM], gV[NELEM];
__device__ __half gA[NELEM];                // attn output, fp16

// ===========================================================================
// Helpers
// ===========================================================================
__device__ __forceinline__ uint32_t smem_u32(const void* p) {
    uint32_t a;
    asm("{ .reg .u64 t; cvta.to.shared.u64 t, %1; cvt.u32.u64 %0, t; }" : "=r"(a) : "l"(p));
    return a;
}

#define LDSM4(R0, R1, R2, R3, ADDR) \
    asm volatile("ldmatrix.sync.aligned.m8n8.x4.shared.b16 {%0,%1,%2,%3}, [%4];" \
                 : "=r"(R0), "=r"(R1), "=r"(R2), "=r"(R3) : "r"(ADDR))

#define LDSM4T(R0, R1, R2, R3, ADDR) \
    asm volatile("ldmatrix.sync.aligned.m8n8.x4.trans.shared.b16 {%0,%1,%2,%3}, [%4];" \
                 : "=r"(R0), "=r"(R1), "=r"(R2), "=r"(R3) : "r"(ADDR))

#define MMA_F16(D, A, B0, B1) \
    asm volatile("mma.sync.aligned.m16n8k16.row.col.f32.f16.f16.f32 " \
                 "{%0,%1,%2,%3}, {%4,%5,%6,%7}, {%8,%9}, {%0,%1,%2,%3};" \
                 : "+f"((D)[0]), "+f"((D)[1]), "+f"((D)[2]), "+f"((D)[3]) \
                 : "r"((A)[0]), "r"((A)[1]), "r"((A)[2]), "r"((A)[3]), "r"(B0), "r"(B1))

#define CP_ASYNC16(DST, SRC) \
    asm volatile("cp.async.cg.shared.global [%0], [%1], 16;" :: "r"(DST), "l"(SRC) : "memory")
#define CP_COMMIT() asm volatile("cp.async.commit_group;" ::: "memory")
#define CP_WAIT(N)  asm volatile("cp.async.wait_group %0;" :: "n"(N) : "memory")

__device__ __forceinline__ uint32_t pack_h2(float a, float b) {
    __half2 h;
    h.x = __float2half_rn(a); h.y = __float2half_rn(b);
    return *(uint32_t*)&h;
}

// fast exp2 on FMA pipe (input already in log2 domain)
__device__ __forceinline__ float fast_exp2(float y) {
    y = fmaxf(y, -126.0f);
    int   e = __float2int_rn(y);
    float f = y - (float)e;
    float p = 1.33336e-3f;
    p = fmaf(p, f, 9.61812e-3f);
    p = fmaf(p, f, 5.55041e-2f);
    p = fmaf(p, f, 2.402265e-1f);
    p = fmaf(p, f, 6.931472e-1f);
    p = fmaf(p, f, 1.0f);
    return __int_as_float((e + 127) << 23) * p;
}

// ===========================================================================
// Convert: X and W's -> fp16.
// ===========================================================================
__global__ void __launch_bounds__(256)
convert_kernel(const float* __restrict__ X,
               const float* __restrict__ Wq, const float* __restrict__ Wk,
               const float* __restrict__ Wv, const float* __restrict__ Wo)
{
    int i = blockIdx.x * 256 + threadIdx.x;       // 0 .. 2097151
    const float4* src;
    __half* dst;
    int off;
    if (i < 1048576) {
        src = (const float4*)X; dst = gX; off = i;
    } else {
        int j = i - 1048576;
        int r = j >> 18;                           // 0..3 -> Wq,Wk,Wv,Wo
        off = j & 0x3FFFF;
        src = (const float4*)(r == 0 ? Wq : r == 1 ? Wk : r == 2 ? Wv : Wo);
        dst = gW + ((size_t)r << 20);
    }
    float4 v = src[off];
    *(uint2*)(dst + (size_t)off * 4) = make_uint2(pack_h2(v.x, v.y), pack_h2(v.z, v.w));
}

// ===========================================================================
// GEMM: C = (A @ W^T + bias) * alpha, single fp16 term.
// CTA 128x128, 8 warps (2x4), warp 64x32, BK=32, 3-stage cp.async, 2 CTAs/SM.
// Uniform wait_group(1) via wrap-around tail produces (non-empty groups).
// MODE 0: f32 out.  MODE 1: fp16 out.
// ===========================================================================
#define GPITCH 40
#define GARR_E (128 * GPITCH)              // 5120 elems per array
#define GSTAGE_E (2 * GARR_E)              // A + B
#define GSMEM_BYTES (3 * GSTAGE_E * 2)     // 61440

__device__ __forceinline__ void gemm_produce(
    uint32_t smb, int stage,
    const __half* __restrict__ A, const __half* __restrict__ B,
    int row0, int col0, int k0, int tid)
{
#pragma unroll
    for (int i = 0; i < 4; ++i) {
        int id  = tid + i * 256;          // 0..1023
        int arr = id >> 9;                // 0:A 1:B
        int rid = (id >> 2) & 127;
        int cc  = id & 3;
        const __half* g = arr ? B : A;
        int grow = (arr ? col0 : row0) + rid;
        const __half* src = g + (size_t)grow * E_DIM + k0 + cc * 8;
        uint32_t dst = smb + (uint32_t)(stage * GSTAGE_E + arr * GARR_E + rid * GPITCH + cc * 8) * 2;
        CP_ASYNC16(dst, src);
    }
}

template <int MODE>
__device__ __forceinline__ void gemm_cp(
    const __half* __restrict__ A, const __half* __restrict__ B,
    const float* __restrict__ bias, float alpha,
    float* __restrict__ Cf, __half* __restrict__ Ch)
{
    extern __shared__ char dynsm[];
    const uint32_t smb = smem_u32(dynsm);
    const int tid  = threadIdx.x;
    const int lane = tid & 31;
    const int wid  = tid >> 5;
    const int wy   = wid >> 2;           // 0..1
    const int wx   = wid & 3;            // 0..3
    const int row0 = blockIdx.y * 128;
    const int col0 = blockIdx.x * 128;

    const int aOffE = (wy * 64 + (lane & 15)) * GPITCH + ((lane >> 4) & 1) * 8;
    const int bOffE = (wx * 32 + (lane & 7) + ((lane >> 4) & 1) * 8) * GPITCH + ((lane >> 3) & 1) * 8;

    float acc[4][4][4];
#pragma unroll
    for (int i = 0; i < 4; i++)
#pragma unroll
        for (int j = 0; j < 4; j++)
#pragma unroll
            for (int k = 0; k < 4; k++) acc[i][j][k] = 0.f;

    // prologue: chunks 0,1 into stages 0,1
    gemm_produce(smb, 0, A, B, row0, col0, 0, tid);
    CP_COMMIT();
    gemm_produce(smb, 1, A, B, row0, col0, 32, tid);
    CP_COMMIT();

    for (int c = 0; c < 32; ++c) {
        CP_WAIT(1);          // chunk c complete (one group per iter, all non-empty)
        __syncthreads();     // visible block-wide; prior readers of target stage done
        // wrap-around produce keeps groups non-empty; tail writes are never read
        gemm_produce(smb, (c + 2) % 3, A, B, row0, col0, ((c + 2) & 31) * 32, tid);
        CP_COMMIT();

        const uint32_t stA = smb + (uint32_t)((c % 3) * GSTAGE_E) * 2;
        const uint32_t aHb = stA;
        const uint32_t bHb = stA + GARR_E * 2;

#pragma unroll
        for (int kb = 0; kb < 2; ++kb) {
            uint32_t bh[4][2];
#pragma unroll
            for (int np = 0; np < 2; ++np) {
                int boe = bOffE + np * 16 * GPITCH + kb * 16;
                LDSM4(bh[2 * np][0], bh[2 * np][1], bh[2 * np + 1][0], bh[2 * np + 1][1],
                      bHb + boe * 2);
            }
#pragma unroll
            for (int mf = 0; mf < 4; ++mf) {
                uint32_t ah[4];
                int aoe = aOffE + mf * 16 * GPITCH + kb * 16;
                LDSM4(ah[0], ah[1], ah[2], ah[3], aHb + aoe * 2);
                MMA_F16(acc[mf][0], ah, bh[0][0], bh[0][1]);
                MMA_F16(acc[mf][1], ah, bh[1][0], bh[1][1]);
                MMA_F16(acc[mf][2], ah, bh[2][0], bh[2][1]);
                MMA_F16(acc[mf][3], ah, bh[3][0], bh[3][1]);
            }
        }
    }
    CP_WAIT(0);   // drain wrap-around produces before exit

    // epilogue
#pragma unroll
    for (int mf = 0; mf < 4; ++mf) {
        int r = row0 + wy * 64 + mf * 16 + (lane >> 2);
#pragma unroll
        for (int nf = 0; nf < 4; ++nf) {
            int col = col0 + wx * 32 + nf * 8 + ((lane & 3) << 1);
            float b0 = bias[col], b1 = bias[col + 1];
            float v0 = (acc[mf][nf][0] + b0) * alpha;
            float v1 = (acc[mf][nf][1] + b1) * alpha;
            float v2 = (acc[mf][nf][2] + b0) * alpha;
            float v3 = (acc[mf][nf][3] + b1) * alpha;
            if (MODE == 0) {
                *(float2*)(Cf + (size_t)r * E_DIM + col)       = make_float2(v0, v1);
                *(float2*)(Cf + (size_t)(r + 8) * E_DIM + col) = make_float2(v2, v3);
            } else {
                *(uint32_t*)(Ch + (size_t)r * E_DIM + col)       = pack_h2(v0, v1);
                *(uint32_t*)(Ch + (size_t)(r + 8) * E_DIM + col) = pack_h2(v2, v3);
            }
        }
    }
}

__global__ void __launch_bounds__(256, 2)
qkv_kernel(const float* __restrict__ bq, const float* __restrict__ bk,
           const float* __restrict__ bv)
{
    const int z = blockIdx.z;
    const __half* Bh = gW + ((size_t)z << 20);
    // Q carries Dh^-0.5 * log2(e) so flash softmax works in exp2 domain
    if (z == 0)      gemm_cp<1>(gX, Bh, bq, 0.125f * 1.44269504f, nullptr, gQ);
    else if (z == 1) gemm_cp<1>(gX, Bh, bk, 1.0f, nullptr, gK);
    else             gemm_cp<1>(gX, Bh, bv, 1.0f, nullptr, gV);
}

__global__ void __launch_bounds__(256, 2)
oproj_kernel(const float* __restrict__ bo, float* __restrict__ out)
{
    gemm_cp<0>(gA, gW + ((size_t)3 << 20), bo, 1.0f, out, nullptr);
}

// ===========================================================================
// Flash attention (causal), fp16 Q/K/V, exp2-domain softmax.
// BR=128 (8 warps x m16), BC=64. 3-stage K/V pipeline; balanced q-tile pairs.
// ===========================================================================
#define FPITCH 72
#define FQ_E   (128 * FPITCH)              // 9216
#define FKV_E  (64 * FPITCH)               // 4608 per array
#define FSTAGE_E (2 * FKV_E)               // K + V per stage
#define FKV0_E FQ_E
#define FSMEM_BYTES ((FKV0_E + 3 * FSTAGE_E) * 2)   // 73728

__device__ __forceinline__ void flash_kv_produce(uint32_t smb, int stage, int j0,
                                                 int b, int colbase, int tid)
{
#pragma unroll
    for (int i = 0; i < 4; ++i) {
        int id  = tid + i * 256;          // 0..1023
        int arr = id >> 9;                // 0:K 1:V
        int rid = (id >> 3) & 63;
        int cc  = id & 7;
        const __half* g = arr ? gV : gK;
        const __half* src = g + ((size_t)(j0 + rid) * B_DIM + b) * E_DIM + colbase + cc * 8;
        uint32_t dst = smb + (uint32_t)(FKV0_E + stage * FSTAGE_E + arr * FKV_E + rid * FPITCH + cc * 8) * 2;
        CP_ASYNC16(dst, src);
    }
}

__device__ __forceinline__ void flash_one(int qt, uint32_t smb, int b, int colbase,
                                          int tid, int lane, int w,
                                          int qOffE, int kOffE, int vOffE)
{
    const int i0 = qt * 128;
    const int ktmax = 2 * qt + 1;         // >= 1 always

    // prologue: group0 = Q + kv0; group1 = kv1
#pragma unroll
    for (int i = 0; i < 4; ++i) {
        int id  = tid + i * 256;          // 0..1023
        int rid = id >> 3;
        int cc  = id & 7;
        const __half* src = gQ + ((size_t)(i0 + rid) * B_DIM + b) * E_DIM + colbase + cc * 8;
        uint32_t dst = smb + (uint32_t)(rid * FPITCH + cc * 8) * 2;
        CP_ASYNC16(dst, src);
    }
    flash_kv_produce(smb, 0, 0, b, colbase, tid);
    CP_COMMIT();
    flash_kv_produce(smb, 1, 64, b, colbase, tid);
    CP_COMMIT();

    float s_m[2] = {-1e9f, -1e9f};
    float s_l[2] = {0.f, 0.f};
    float o[8][4];
#pragma unroll
    for (int i = 0; i < 8; i++)
#pragma unroll
        for (int j = 0; j < 4; j++) o[i][j] = 0.f;

    const int rg0 = i0 + w * 16 + (lane >> 2);
    const uint32_t qB = smb;

    for (int kt = 0; kt <= ktmax; ++kt) {
        CP_WAIT(1);           // tile kt landed (one non-empty group per iter)
        __syncthreads();
        {   // wrap-around produce (clamped index; unread duplicates at tail)
            int ktn = (kt + 2 <= ktmax) ? (kt + 2) : ktmax;
            flash_kv_produce(smb, (kt + 2) % 3, ktn * 64, b, colbase, tid);
            CP_COMMIT();
        }

        const int j0 = kt * 64;
        const uint32_t stKV = smb + (uint32_t)(FKV0_E + (kt % 3) * FSTAGE_E) * 2;
        const uint32_t kB = stKV;
        const uint32_t vB = stKV + FKV_E * 2;

        // ---- S = Q @ K^T (single term, log2-domain scores) ----
        float s[8][4];
#pragma unroll
        for (int i = 0; i < 8; i++)
#pragma unroll
            for (int j = 0; j < 4; j++) s[i][j] = 0.f;

#pragma unroll
        for (int kb = 0; kb < 4; ++kb) {
            uint32_t a[4];
            LDSM4(a[0], a[1], a[2], a[3], qB + (qOffE + kb * 16) * 2);
            uint32_t kh[4][4];
#pragma unroll
            for (int np = 0; np < 4; ++np) {
                int boe = kOffE + np * 16 * FPITCH + kb * 16;
                LDSM4(kh[np][0], kh[np][1], kh[np][2], kh[np][3], kB + boe * 2);
            }
#pragma unroll
            for (int np = 0; np < 4; ++np) {
                MMA_F16(s[2 * np],     a, kh[np][0], kh[np][1]);
                MMA_F16(s[2 * np + 1], a, kh[np][2], kh[np][3]);
            }
        }

        // ---- causal mask ----
        if (j0 + 63 > i0 + w * 16) {
#pragma unroll
            for (int nf = 0; nf < 8; ++nf) {
                int j = j0 + nf * 8 + ((lane & 3) << 1);
                if (j     > rg0)     s[nf][0] = -1e9f;
                if (j + 1 > rg0)     s[nf][1] = -1e9f;
                if (j     > rg0 + 8) s[nf][2] = -1e9f;
                if (j + 1 > rg0 + 8) s[nf][3] = -1e9f;
            }
        }

        // ---- online softmax in exp2 domain ----
#pragma unroll
        for (int half = 0; half < 2; ++half) {
            const int e0 = half * 2, e1 = half * 2 + 1;
            float vmax = -1e9f;
#pragma unroll
            for (int nf = 0; nf < 8; ++nf)
                vmax = fmaxf(vmax, fmaxf(s[nf][e0], s[nf][e1]));
            vmax = fmaxf(vmax, __shfl_xor_sync(0xffffffffu, vmax, 1));
            vmax = fmaxf(vmax, __shfl_xor_sync(0xffffffffu, vmax, 2));
            float mnew = fmaxf(s_m[half], vmax);
            float corr = fast_exp2(s_m[half] - mnew);
            float rsum = 0.f;
#pragma unroll
            for (int nf = 0; nf < 8; ++nf) {
                float p0 = fast_exp2(s[nf][e0] - mnew);
                float p1 = fast_exp2(s[nf][e1] - mnew);
                s[nf][e0] = p0; s[nf][e1] = p1;
                rsum += p0 + p1;
            }
            rsum += __shfl_xor_sync(0xffffffffu, rsum, 1);
            rsum += __shfl_xor_sync(0xffffffffu, rsum, 2);
            s_l[half] = s_l[half] * corr + rsum;
            s_m[half] = mnew;
#pragma unroll
            for (int nf = 0; nf < 8; ++nf) {
                o[nf][e0] *= corr;
                o[nf][e1] *= corr;
            }
        }

        // ---- O += P @ V (single term; P rounded at pack) ----
#pragma unroll
        for (int kc = 0; kc < 4; ++kc) {
            uint32_t ph[4];
            ph[0] = pack_h2(s[2 * kc][0],     s[2 * kc][1]);
            ph[1] = pack_h2(s[2 * kc][2],     s[2 * kc][3]);
            ph[2] = pack_h2(s[2 * kc + 1][0], s[2 * kc + 1][1]);
            ph[3] = pack_h2(s[2 * kc + 1][2], s[2 * kc + 1][3]);
            uint32_t wh[4][4];
#pragma unroll
            for (int np = 0; np < 4; ++np) {
                int voe = vOffE + kc * 16 * FPITCH + np * 16;
                LDSM4T(wh[np][0], wh[np][1], wh[np][2], wh[np][3], vB + voe * 2);
            }
#pragma unroll
            for (int np = 0; np < 4; ++np) {
                MMA_F16(o[2 * np],     ph, wh[np][0], wh[np][1]);
                MMA_F16(o[2 * np + 1], ph, wh[np][2], wh[np][3]);
            }
        }
    }
    CP_WAIT(0);        // drain wrap-around produces (next call reuses stages)
    __syncthreads();   // smem reads done before caller refills Q region

    // ---- finalize: attn = o / l, stored as fp16 ----
    const float inv0 = 1.f / s_l[0];
    const float inv1 = 1.f / s_l[1];
#pragma unroll
    for (int nf = 0; nf < 8; ++nf) {
        int col = colbase + nf * 8 + ((lane & 3) << 1);
        size_t r0off = ((size_t)rg0 * B_DIM + b) * E_DIM + col;
        size_t r1off = ((size_t)(rg0 + 8) * B_DIM + b) * E_DIM + col;
        *(uint32_t*)(gA + r0off) = pack_h2(o[nf][0] * inv0, o[nf][1] * inv0);
        *(uint32_t*)(gA + r1off) = pack_h2(o[nf][2] * inv1, o[nf][3] * inv1);
    }
}

__global__ void __launch_bounds__(256)
flash_mma_kernel()
{
    extern __shared__ char dynsm[];
    const uint32_t smb = smem_u32(dynsm);

    const int tid  = threadIdx.x;
    const int lane = tid & 31;
    const int w    = tid >> 5;
    const int pair = blockIdx.x;          // 0..7
    const int head = blockIdx.y;          // 0..31
    const int b    = head >> 4;
    const int h    = head & 15;
    const int colbase = h * DH;

    const int qOffE = (w * 16 + (lane & 15)) * FPITCH + ((lane >> 4) & 1) * 8;
    const int kOffE = ((lane & 7) + ((lane >> 4) & 1) * 8) * FPITCH + ((lane >> 3) & 1) * 8;
    const int vOffE = ((lane & 7) + ((lane >> 3) & 1) * 8) * FPITCH + ((lane >> 4) & 1) * 8;

    flash_one(pair,      smb, b, colbase, tid, lane, w, qOffE, kOffE, vOffE);
    flash_one(15 - pair, smb, b, colbase, tid, lane, w, qOffE, kOffE, vOffE);
}

// ===========================================================================
// kernel_launch
// Inputs: query, Wq, bq, Wk, bk, Wv, bv, Wo, bo, attn_mask (ignored: causal)
// ===========================================================================
extern "C" void kernel_launch(void* const* d_in, const int* in_sizes, int n_in,
                              void* d_out, int out_size)
{
    const float* query = (const float*)d_in[0];
    const float* Wq    = (const float*)d_in[1];
    const float* bq    = (const float*)d_in[2];
    const float* Wk    = (const float*)d_in[3];
    const float* bk    = (const float*)d_in[4];
    const float* Wv    = (const float*)d_in[5];
    const float* bv    = (const float*)d_in[6];
    const float* Wo    = (const float*)d_in[7];
    const float* bo    = (const float*)d_in[8];
    float* out = (float*)d_out;

    cudaFuncSetAttribute(qkv_kernel, cudaFuncAttributeMaxDynamicSharedMemorySize, GSMEM_BYTES);
    cudaFuncSetAttribute(oproj_kernel, cudaFuncAttributeMaxDynamicSharedMemorySize, GSMEM_BYTES);
    cudaFuncSetAttribute(flash_mma_kernel, cudaFuncAttributeMaxDynamicSharedMemorySize, FSMEM_BYTES);

    // X and weights -> fp16
    convert_kernel<<<8192, 256>>>(query, Wq, Wk, Wv, Wo);

    // QKV projections (all 1-term) -> fp16 q,k,v
    qkv_kernel<<<dim3(E_DIM / 128, MROWS / 128, 3), 256, GSMEM_BYTES>>>(bq, bk, bv);

    // causal flash attention: 8 balanced q-tile pairs x 32 heads
    flash_mma_kernel<<<dim3(8, B_DIM * H_DIM), 256, FSMEM_BYTES>>>();

    // output projection -> f32 out
    oproj_kernel<<<dim3(E_DIM / 128, MROWS / 128), 256, GSMEM_BYTES>>>(bo, out);
}

// round 11
// speedup vs baseline: 2.3461x; 1.0187x over previous
#include <cuda_runtime.h>
#include <cuda_fp16.h>
#include <math.h>
#include <stdint.h>

// Problem constants
#define T_DIM 2048
#define B_DIM 2
#define E_DIM 1024
#define H_DIM 16
#define DH    64
#define MROWS (T_DIM * B_DIM)   // 4096
#define NELEM (MROWS * E_DIM)   // 4194304

// Scratch (device globals — no allocation allowed). All fp16.
__device__ __half gX[NELEM];                // input X, fp16
__device__ __half gW[NELEM];                // Wq,Wk,Wv,Wo fp16 (1M each)
__device__ __half gQ[NELEM], gK[NELEM], gV[NELEM];
__device__ __half gA[NELEM];                // attn output, fp16

// ===========================================================================
// Helpers
// ===========================================================================
__device__ __forceinline__ uint32_t smem_u32(const void* p) {
    uint32_t a;
    asm("{ .reg .u64 t; cvta.to.shared.u64 t, %1; cvt.u32.u64 %0, t; }" : "=r"(a) : "l"(p));
    return a;
}

#define LDSM4(R0, R1, R2, R3, ADDR) \
    asm volatile("ldmatrix.sync.aligned.m8n8.x4.shared.b16 {%0,%1,%2,%3}, [%4];" \
                 : "=r"(R0), "=r"(R1), "=r"(R2), "=r"(R3) : "r"(ADDR))

#define LDSM4T(R0, R1, R2, R3, ADDR) \
    asm volatile("ldmatrix.sync.aligned.m8n8.x4.trans.shared.b16 {%0,%1,%2,%3}, [%4];" \
                 : "=r"(R0), "=r"(R1), "=r"(R2), "=r"(R3) : "r"(ADDR))

#define MMA_F16(D, A, B0, B1) \
    asm volatile("mma.sync.aligned.m16n8k16.row.col.f32.f16.f16.f32 " \
                 "{%0,%1,%2,%3}, {%4,%5,%6,%7}, {%8,%9}, {%0,%1,%2,%3};" \
                 : "+f"((D)[0]), "+f"((D)[1]), "+f"((D)[2]), "+f"((D)[3]) \
                 : "r"((A)[0]), "r"((A)[1]), "r"((A)[2]), "r"((A)[3]), "r"(B0), "r"(B1))

#define CP_ASYNC16(DST, SRC) \
    asm volatile("cp.async.cg.shared.global [%0], [%1], 16;" :: "r"(DST), "l"(SRC) : "memory")
#define CP_COMMIT() asm volatile("cp.async.commit_group;" ::: "memory")
#define CP_WAIT(N)  asm volatile("cp.async.wait_group %0;" :: "n"(N) : "memory")

__device__ __forceinline__ uint32_t pack_h2(float a, float b) {
    __half2 h;
    h.x = __float2half_rn(a); h.y = __float2half_rn(b);
    return *(uint32_t*)&h;
}

// fast exp2 on FMA pipe (input already in log2 domain)
__device__ __forceinline__ float fast_exp2(float y) {
    y = fmaxf(y, -126.0f);
    int   e = __float2int_rn(y);
    float f = y - (float)e;
    float p = 1.33336e-3f;
    p = fmaf(p, f, 9.61812e-3f);
    p = fmaf(p, f, 5.55041e-2f);
    p = fmaf(p, f, 2.402265e-1f);
    p = fmaf(p, f, 6.931472e-1f);
    p = fmaf(p, f, 1.0f);
    return __int_as_float((e + 127) << 23) * p;
}

// exp2 on the MUFU pipe (idle in flash) — balances FMA-pipe pressure
__device__ __forceinline__ float mufu_exp2(float y) {
    float r;
    asm("ex2.approx.f32 %0, %1;" : "=f"(r) : "f"(y));
    return r;
}

// ===========================================================================
// Convert: X and W's -> fp16.
// ===========================================================================
__global__ void __launch_bounds__(256)
convert_kernel(const float* __restrict__ X,
               const float* __restrict__ Wq, const float* __restrict__ Wk,
               const float* __restrict__ Wv, const float* __restrict__ Wo)
{
    int i = blockIdx.x * 256 + threadIdx.x;       // 0 .. 2097151
    const float4* src;
    __half* dst;
    int off;
    if (i < 1048576) {
        src = (const float4*)X; dst = gX; off = i;
    } else {
        int j = i - 1048576;
        int r = j >> 18;                           // 0..3 -> Wq,Wk,Wv,Wo
        off = j & 0x3FFFF;
        src = (const float4*)(r == 0 ? Wq : r == 1 ? Wk : r == 2 ? Wv : Wo);
        dst = gW + ((size_t)r << 20);
    }
    float4 v = src[off];
    *(uint2*)(dst + (size_t)off * 4) = make_uint2(pack_h2(v.x, v.y), pack_h2(v.z, v.w));
}

// ===========================================================================
// GEMM: C = (A @ W^T + bias) * alpha, single fp16 term.
// CTA 128x128, 8 warps (2x4), warp 64x32, BK=32, 3-stage cp.async, 2 CTAs/SM.
// Uniform wait_group(1) via wrap-around tail produces (non-empty groups).
// MODE 0: f32 out.  MODE 1: fp16 out.
// ===========================================================================
#define GPITCH 40
#define GARR_E (128 * GPITCH)              // 5120 elems per array
#define GSTAGE_E (2 * GARR_E)              // A + B
#define GSMEM_BYTES (3 * GSTAGE_E * 2)     // 61440

__device__ __forceinline__ void gemm_produce(
    uint32_t smb, int stage,
    const __half* __restrict__ A, const __half* __restrict__ B,
    int row0, int col0, int k0, int tid)
{
#pragma unroll
    for (int i = 0; i < 4; ++i) {
        int id  = tid + i * 256;          // 0..1023
        int arr = id >> 9;                // 0:A 1:B
        int rid = (id >> 2) & 127;
        int cc  = id & 3;
        const __half* g = arr ? B : A;
        int grow = (arr ? col0 : row0) + rid;
        const __half* src = g + (size_t)grow * E_DIM + k0 + cc * 8;
        uint32_t dst = smb + (uint32_t)(stage * GSTAGE_E + arr * GARR_E + rid * GPITCH + cc * 8) * 2;
        CP_ASYNC16(dst, src);
    }
}

template <int MODE>
__device__ __forceinline__ void gemm_cp(
    const __half* __restrict__ A, const __half* __restrict__ B,
    const float* __restrict__ bias, float alpha,
    float* __restrict__ Cf, __half* __restrict__ Ch)
{
    extern __shared__ char dynsm[];
    const uint32_t smb = smem_u32(dynsm);
    const int tid  = threadIdx.x;
    const int lane = tid & 31;
    const int wid  = tid >> 5;
    const int wy   = wid >> 2;           // 0..1
    const int wx   = wid & 3;            // 0..3
    const int row0 = blockIdx.y * 128;
    const int col0 = blockIdx.x * 128;

    const int aOffE = (wy * 64 + (lane & 15)) * GPITCH + ((lane >> 4) & 1) * 8;
    const int bOffE = (wx * 32 + (lane & 7) + ((lane >> 4) & 1) * 8) * GPITCH + ((lane >> 3) & 1) * 8;

    float acc[4][4][4];
#pragma unroll
    for (int i = 0; i < 4; i++)
#pragma unroll
        for (int j = 0; j < 4; j++)
#pragma unroll
            for (int k = 0; k < 4; k++) acc[i][j][k] = 0.f;

    // prologue: chunks 0,1 into stages 0,1
    gemm_produce(smb, 0, A, B, row0, col0, 0, tid);
    CP_COMMIT();
    gemm_produce(smb, 1, A, B, row0, col0, 32, tid);
    CP_COMMIT();

    for (int c = 0; c < 32; ++c) {
        CP_WAIT(1);          // chunk c complete (one group per iter, all non-empty)
        __syncthreads();     // visible block-wide; prior readers of target stage done
        // wrap-around produce keeps groups non-empty; tail writes are never read
        gemm_produce(smb, (c + 2) % 3, A, B, row0, col0, ((c + 2) & 31) * 32, tid);
        CP_COMMIT();

        const uint32_t stA = smb + (uint32_t)((c % 3) * GSTAGE_E) * 2;
        const uint32_t aHb = stA;
        const uint32_t bHb = stA + GARR_E * 2;

#pragma unroll
        for (int kb = 0; kb < 2; ++kb) {
            uint32_t bh[4][2];
#pragma unroll
            for (int np = 0; np < 2; ++np) {
                int boe = bOffE + np * 16 * GPITCH + kb * 16;
                LDSM4(bh[2 * np][0], bh[2 * np][1], bh[2 * np + 1][0], bh[2 * np + 1][1],
                      bHb + boe * 2);
            }
#pragma unroll
            for (int mf = 0; mf < 4; ++mf) {
                uint32_t ah[4];
                int aoe = aOffE + mf * 16 * GPITCH + kb * 16;
                LDSM4(ah[0], ah[1], ah[2], ah[3], aHb + aoe * 2);
                MMA_F16(acc[mf][0], ah, bh[0][0], bh[0][1]);
                MMA_F16(acc[mf][1], ah, bh[1][0], bh[1][1]);
                MMA_F16(acc[mf][2], ah, bh[2][0], bh[2][1]);
                MMA_F16(acc[mf][3], ah, bh[3][0], bh[3][1]);
            }
        }
    }
    CP_WAIT(0);   // drain wrap-around produces before exit

    // epilogue
#pragma unroll
    for (int mf = 0; mf < 4; ++mf) {
        int r = row0 + wy * 64 + mf * 16 + (lane >> 2);
#pragma unroll
        for (int nf = 0; nf < 4; ++nf) {
            int col = col0 + wx * 32 + nf * 8 + ((lane & 3) << 1);
            float b0 = bias[col], b1 = bias[col + 1];
            float v0 = (acc[mf][nf][0] + b0) * alpha;
            float v1 = (acc[mf][nf][1] + b1) * alpha;
            float v2 = (acc[mf][nf][2] + b0) * alpha;
            float v3 = (acc[mf][nf][3] + b1) * alpha;
            if (MODE == 0) {
                *(float2*)(Cf + (size_t)r * E_DIM + col)       = make_float2(v0, v1);
                *(float2*)(Cf + (size_t)(r + 8) * E_DIM + col) = make_float2(v2, v3);
            } else {
                *(uint32_t*)(Ch + (size_t)r * E_DIM + col)       = pack_h2(v0, v1);
                *(uint32_t*)(Ch + (size_t)(r + 8) * E_DIM + col) = pack_h2(v2, v3);
            }
        }
    }
}

__global__ void __launch_bounds__(256, 2)
qkv_kernel(const float* __restrict__ bq, const float* __restrict__ bk,
           const float* __restrict__ bv)
{
    const int z = blockIdx.z;
    const __half* Bh = gW + ((size_t)z << 20);
    // Q carries Dh^-0.5 * log2(e) so flash softmax works in exp2 domain
    if (z == 0)      gemm_cp<1>(gX, Bh, bq, 0.125f * 1.44269504f, nullptr, gQ);
    else if (z == 1) gemm_cp<1>(gX, Bh, bk, 1.0f, nullptr, gK);
    else             gemm_cp<1>(gX, Bh, bv, 1.0f, nullptr, gV);
}

__global__ void __launch_bounds__(256, 2)
oproj_kernel(const float* __restrict__ bo, float* __restrict__ out)
{
    gemm_cp<0>(gA, gW + ((size_t)3 << 20), bo, 1.0f, out, nullptr);
}

// ===========================================================================
// Flash attention (causal), fp16 Q/K/V, exp2-domain softmax.
// BR=128 (8 warps x m16), BC=64. 3-stage K/V pipeline; balanced q-tile pairs.
// Softmax: hybrid MUFU/FMA exp + warp-uniform rescale skip.
// ===========================================================================
#define FPITCH 72
#define FQ_E   (128 * FPITCH)              // 9216
#define FKV_E  (64 * FPITCH)               // 4608 per array
#define FSTAGE_E (2 * FKV_E)               // K + V per stage
#define FKV0_E FQ_E
#define FSMEM_BYTES ((FKV0_E + 3 * FSTAGE_E) * 2)   // 73728

__device__ __forceinline__ void flash_kv_produce(uint32_t smb, int stage, int j0,
                                                 int b, int colbase, int tid)
{
#pragma unroll
    for (int i = 0; i < 4; ++i) {
        int id  = tid + i * 256;          // 0..1023
        int arr = id >> 9;                // 0:K 1:V
        int rid = (id >> 3) & 63;
        int cc  = id & 7;
        const __half* g = arr ? gV : gK;
        const __half* src = g + ((size_t)(j0 + rid) * B_DIM + b) * E_DIM + colbase + cc * 8;
        uint32_t dst = smb + (uint32_t)(FKV0_E + stage * FSTAGE_E + arr * FKV_E + rid * FPITCH + cc * 8) * 2;
        CP_ASYNC16(dst, src);
    }
}

__device__ __forceinline__ void flash_one(int qt, uint32_t smb, int b, int colbase,
                                          int tid, int lane, int w,
                                          int qOffE, int kOffE, int vOffE)
{
    const int i0 = qt * 128;
    const int ktmax = 2 * qt + 1;         // >= 1 always

    // prologue: group0 = Q + kv0; group1 = kv1
#pragma unroll
    for (int i = 0; i < 4; ++i) {
        int id  = tid + i * 256;          // 0..1023
        int rid = id >> 3;
        int cc  = id & 7;
        const __half* src = gQ + ((size_t)(i0 + rid) * B_DIM + b) * E_DIM + colbase + cc * 8;
        uint32_t dst = smb + (uint32_t)(rid * FPITCH + cc * 8) * 2;
        CP_ASYNC16(dst, src);
    }
    flash_kv_produce(smb, 0, 0, b, colbase, tid);
    CP_COMMIT();
    flash_kv_produce(smb, 1, 64, b, colbase, tid);
    CP_COMMIT();

    float s_m[2] = {-1e9f, -1e9f};
    float s_l[2] = {0.f, 0.f};
    float o[8][4];
#pragma unroll
    for (int i = 0; i < 8; i++)
#pragma unroll
        for (int j = 0; j < 4; j++) o[i][j] = 0.f;

    const int rg0 = i0 + w * 16 + (lane >> 2);
    const uint32_t qB = smb;

    for (int kt = 0; kt <= ktmax; ++kt) {
        CP_WAIT(1);           // tile kt landed (one non-empty group per iter)
        __syncthreads();
        {   // wrap-around produce (clamped index; unread duplicates at tail)
            int ktn = (kt + 2 <= ktmax) ? (kt + 2) : ktmax;
            flash_kv_produce(smb, (kt + 2) % 3, ktn * 64, b, colbase, tid);
            CP_COMMIT();
        }

        const int j0 = kt * 64;
        const uint32_t stKV = smb + (uint32_t)(FKV0_E + (kt % 3) * FSTAGE_E) * 2;
        const uint32_t kB = stKV;
        const uint32_t vB = stKV + FKV_E * 2;

        // ---- S = Q @ K^T (single term, log2-domain scores) ----
        float s[8][4];
#pragma unroll
        for (int i = 0; i < 8; i++)
#pragma unroll
            for (int j = 0; j < 4; j++) s[i][j] = 0.f;

#pragma unroll
        for (int kb = 0; kb < 4; ++kb) {
            uint32_t a[4];
            LDSM4(a[0], a[1], a[2], a[3], qB + (qOffE + kb * 16) * 2);
            uint32_t kh[4][4];
#pragma unroll
            for (int np = 0; np < 4; ++np) {
                int boe = kOffE + np * 16 * FPITCH + kb * 16;
                LDSM4(kh[np][0], kh[np][1], kh[np][2], kh[np][3], kB + boe * 2);
            }
#pragma unroll
            for (int np = 0; np < 4; ++np) {
                MMA_F16(s[2 * np],     a, kh[np][0], kh[np][1]);
                MMA_F16(s[2 * np + 1], a, kh[np][2], kh[np][3]);
            }
        }

        // ---- causal mask ----
        if (j0 + 63 > i0 + w * 16) {
#pragma unroll
            for (int nf = 0; nf < 8; ++nf) {
                int j = j0 + nf * 8 + ((lane & 3) << 1);
                if (j     > rg0)     s[nf][0] = -1e9f;
                if (j + 1 > rg0)     s[nf][1] = -1e9f;
                if (j     > rg0 + 8) s[nf][2] = -1e9f;
                if (j + 1 > rg0 + 8) s[nf][3] = -1e9f;
            }
        }

        // ---- online softmax in exp2 domain ----
        float vmax[2];
#pragma unroll
        for (int half = 0; half < 2; ++half) {
            const int e0 = half * 2, e1 = half * 2 + 1;
            float m = -1e9f;
#pragma unroll
            for (int nf = 0; nf < 8; ++nf)
                m = fmaxf(m, fmaxf(s[nf][e0], s[nf][e1]));
            m = fmaxf(m, __shfl_xor_sync(0xffffffffu, m, 1));
            m = fmaxf(m, __shfl_xor_sync(0xffffffffu, m, 2));
            vmax[half] = m;
        }
        // warp-uniform skip: if max didn't move anywhere in this warp,
        // corr == 1 exactly -> no o-rescale, no corr-exp.
        const bool noresc = __all_sync(0xffffffffu,
                                       vmax[0] <= s_m[0] && vmax[1] <= s_m[1]);
#pragma unroll
        for (int half = 0; half < 2; ++half) {
            const int e0 = half * 2, e1 = half * 2 + 1;
            const float mnew = noresc ? s_m[half] : fmaxf(s_m[half], vmax[half]);
            float rsum = 0.f;
#pragma unroll
            for (int nf = 0; nf < 8; ++nf) {
                // hybrid: half the exps on MUFU (idle pipe), half on FMA poly
                float p0 = mufu_exp2(s[nf][e0] - mnew);
                float p1 = fast_exp2(s[nf][e1] - mnew);
                s[nf][e0] = p0; s[nf][e1] = p1;
                rsum += p0 + p1;
            }
            rsum += __shfl_xor_sync(0xffffffffu, rsum, 1);
            rsum += __shfl_xor_sync(0xffffffffu, rsum, 2);
            if (noresc) {
                s_l[half] += rsum;
            } else {
                float corr = fast_exp2(s_m[half] - mnew);
                s_l[half] = s_l[half] * corr + rsum;
                s_m[half] = mnew;
#pragma unroll
                for (int nf = 0; nf < 8; ++nf) {
                    o[nf][e0] *= corr;
                    o[nf][e1] *= corr;
                }
            }
        }

        // ---- O += P @ V (single term; P rounded at pack) ----
#pragma unroll
        for (int kc = 0; kc < 4; ++kc) {
            uint32_t ph[4];
            ph[0] = pack_h2(s[2 * kc][0],     s[2 * kc][1]);
            ph[1] = pack_h2(s[2 * kc][2],     s[2 * kc][3]);
            ph[2] = pack_h2(s[2 * kc + 1][0], s[2 * kc + 1][1]);
            ph[3] = pack_h2(s[2 * kc + 1][2], s[2 * kc + 1][3]);
            uint32_t wh[4][4];
#pragma unroll
            for (int np = 0; np < 4; ++np) {
                int voe = vOffE + kc * 16 * FPITCH + np * 16;
                LDSM4T(wh[np][0], wh[np][1], wh[np][2], wh[np][3], vB + voe * 2);
            }
#pragma unroll
            for (int np = 0; np < 4; ++np) {
                MMA_F16(o[2 * np],     ph, wh[np][0], wh[np][1]);
                MMA_F16(o[2 * np + 1], ph, wh[np][2], wh[np][3]);
            }
        }
    }
    CP_WAIT(0);        // drain wrap-around produces (next call reuses stages)
    __syncthreads();   // smem reads done before caller refills Q region

    // ---- finalize: attn = o / l, stored as fp16 ----
    const float inv0 = 1.f / s_l[0];
    const float inv1 = 1.f / s_l[1];
#pragma unroll
    for (int nf = 0; nf < 8; ++nf) {
        int col = colbase + nf * 8 + ((lane & 3) << 1);
        size_t r0off = ((size_t)rg0 * B_DIM + b) * E_DIM + col;
        size_t r1off = ((size_t)(rg0 + 8) * B_DIM + b) * E_DIM + col;
        *(uint32_t*)(gA + r0off) = pack_h2(o[nf][0] * inv0, o[nf][1] * inv0);
        *(uint32_t*)(gA + r1off) = pack_h2(o[nf][2] * inv1, o[nf][3] * inv1);
    }
}

__global__ void __launch_bounds__(256)
flash_mma_kernel()
{
    extern __shared__ char dynsm[];
    const uint32_t smb = smem_u32(dynsm);

    const int tid  = threadIdx.x;
    const int lane = tid & 31;
    const int w    = tid >> 5;
    const int pair = blockIdx.x;          // 0..7
    const int head = blockIdx.y;          // 0..31
    const int b    = head >> 4;
    const int h    = head & 15;
    const int colbase = h * DH;

    const int qOffE = (w * 16 + (lane & 15)) * FPITCH + ((lane >> 4) & 1) * 8;
    const int kOffE = ((lane & 7) + ((lane >> 4) & 1) * 8) * FPITCH + ((lane >> 3) & 1) * 8;
    const int vOffE = ((lane & 7) + ((lane >> 3) & 1) * 8) * FPITCH + ((lane >> 4) & 1) * 8;

    flash_one(pair,      smb, b, colbase, tid, lane, w, qOffE, kOffE, vOffE);
    flash_one(15 - pair, smb, b, colbase, tid, lane, w, qOffE, kOffE, vOffE);
}

// ===========================================================================
// kernel_launch
// Inputs: query, Wq, bq, Wk, bk, Wv, bv, Wo, bo, attn_mask (ignored: causal)
// ===========================================================================
extern "C" void kernel_launch(void* const* d_in, const int* in_sizes, int n_in,
                              void* d_out, int out_size)
{
    const float* query = (const float*)d_in[0];
    const float* Wq    = (const float*)d_in[1];
    const float* bq    = (const float*)d_in[2];
    const float* Wk    = (const float*)d_in[3];
    const float* bk    = (const float*)d_in[4];
    const float* Wv    = (const float*)d_in[5];
    const float* bv    = (const float*)d_in[6];
    const float* Wo    = (const float*)d_in[7];
    const float* bo    = (const float*)d_in[8];
    float* out = (float*)d_out;

    cudaFuncSetAttribute(qkv_kernel, cudaFuncAttributeMaxDynamicSharedMemorySize, GSMEM_BYTES);
    cudaFuncSetAttribute(oproj_kernel, cudaFuncAttributeMaxDynamicSharedMemorySize, GSMEM_BYTES);
    cudaFuncSetAttribute(flash_mma_kernel, cudaFuncAttributeMaxDynamicSharedMemorySize, FSMEM_BYTES);

    // X and weights -> fp16
    convert_kernel<<<8192, 256>>>(query, Wq, Wk, Wv, Wo);

    // QKV projections (all 1-term) -> fp16 q,k,v
    qkv_kernel<<<dim3(E_DIM / 128, MROWS / 128, 3), 256, GSMEM_BYTES>>>(bq, bk, bv);

    // causal flash attention: 8 balanced q-tile pairs x 32 heads
    flash_mma_kernel<<<dim3(8, B_DIM * H_DIM), 256, FSMEM_BYTES>>>();

    // output projection -> f32 out
    oproj_kernel<<<dim3(E_DIM / 128, MROWS / 128), 256, GSMEM_BYTES>>>(bo, out);
}

// round 12
// speedup vs baseline: 2.4306x; 1.0360x over previous
#include <cuda_runtime.h>
#include <cuda_fp16.h>
#include <math.h>
#include <stdint.h>

// Problem constants
#define T_DIM 2048
#define B_DIM 2
#define E_DIM 1024
#define H_DIM 16
#define DH    64
#define MROWS (T_DIM * B_DIM)   // 4096
#define NELEM (MROWS * E_DIM)   // 4194304

// Scratch (device globals — no allocation allowed). All fp16.
__device__ __half gX[NELEM];                // input X, fp16
__device__ __half gW[NELEM];                // Wq,Wk,Wv,Wo fp16 (1M each)
__device__ __half gQ[NELEM], gK[NELEM], gV[NELEM];
__device__ __half gA[NELEM];                // attn output, fp16

// ===========================================================================
// Helpers
// ===========================================================================
__device__ __forceinline__ uint32_t smem_u32(const void* p) {
    uint32_t a;
    asm("{ .reg .u64 t; cvta.to.shared.u64 t, %1; cvt.u32.u64 %0, t; }" : "=r"(a) : "l"(p));
    return a;
}

#define LDSM4(R0, R1, R2, R3, ADDR) \
    asm volatile("ldmatrix.sync.aligned.m8n8.x4.shared.b16 {%0,%1,%2,%3}, [%4];" \
                 : "=r"(R0), "=r"(R1), "=r"(R2), "=r"(R3) : "r"(ADDR))

#define LDSM4T(R0, R1, R2, R3, ADDR) \
    asm volatile("ldmatrix.sync.aligned.m8n8.x4.trans.shared.b16 {%0,%1,%2,%3}, [%4];" \
                 : "=r"(R0), "=r"(R1), "=r"(R2), "=r"(R3) : "r"(ADDR))

#define MMA_F16(D, A, B0, B1) \
    asm volatile("mma.sync.aligned.m16n8k16.row.col.f32.f16.f16.f32 " \
                 "{%0,%1,%2,%3}, {%4,%5,%6,%7}, {%8,%9}, {%0,%1,%2,%3};" \
                 : "+f"((D)[0]), "+f"((D)[1]), "+f"((D)[2]), "+f"((D)[3]) \
                 : "r"((A)[0]), "r"((A)[1]), "r"((A)[2]), "r"((A)[3]), "r"(B0), "r"(B1))

#define CP_ASYNC16(DST, SRC) \
    asm volatile("cp.async.cg.shared.global [%0], [%1], 16;" :: "r"(DST), "l"(SRC) : "memory")
#define CP_COMMIT() asm volatile("cp.async.commit_group;" ::: "memory")
#define CP_WAIT(N)  asm volatile("cp.async.wait_group %0;" :: "n"(N) : "memory")

__device__ __forceinline__ uint32_t pack_h2(float a, float b) {
    __half2 h;
    h.x = __float2half_rn(a); h.y = __float2half_rn(b);
    return *(uint32_t*)&h;
}

// fast exp2 on FMA pipe (input already in log2 domain)
__device__ __forceinline__ float fast_exp2(float y) {
    y = fmaxf(y, -126.0f);
    int   e = __float2int_rn(y);
    float f = y - (float)e;
    float p = 1.33336e-3f;
    p = fmaf(p, f, 9.61812e-3f);
    p = fmaf(p, f, 5.55041e-2f);
    p = fmaf(p, f, 2.402265e-1f);
    p = fmaf(p, f, 6.931472e-1f);
    p = fmaf(p, f, 1.0f);
    return __int_as_float((e + 127) << 23) * p;
}

// exp2 on the MUFU pipe (idle in flash) — balances FMA-pipe pressure
__device__ __forceinline__ float mufu_exp2(float y) {
    float r;
    asm("ex2.approx.f32 %0, %1;" : "=f"(r) : "f"(y));
    return r;
}

// ===========================================================================
// Convert: X and W's -> fp16.
// ===========================================================================
__global__ void __launch_bounds__(256)
convert_kernel(const float* __restrict__ X,
               const float* __restrict__ Wq, const float* __restrict__ Wk,
               const float* __restrict__ Wv, const float* __restrict__ Wo)
{
    int i = blockIdx.x * 256 + threadIdx.x;       // 0 .. 2097151
    const float4* src;
    __half* dst;
    int off;
    if (i < 1048576) {
        src = (const float4*)X; dst = gX; off = i;
    } else {
        int j = i - 1048576;
        int r = j >> 18;                           // 0..3 -> Wq,Wk,Wv,Wo
        off = j & 0x3FFFF;
        src = (const float4*)(r == 0 ? Wq : r == 1 ? Wk : r == 2 ? Wv : Wo);
        dst = gW + ((size_t)r << 20);
    }
    float4 v = src[off];
    *(uint2*)(dst + (size_t)off * 4) = make_uint2(pack_h2(v.x, v.y), pack_h2(v.z, v.w));
}

// ===========================================================================
// GEMM: C = (A @ W^T + bias) * alpha, single fp16 term.
// CTA 128x128, 8 warps (2x4), warp 64x32, BK=64, 3-stage cp.async, 2 CTAs/SM.
// 16 chunks -> 16 barriers (was 32). Uniform wait_group(1) via wrap-around
// tail produces (non-empty groups; tail writes land in stages never re-read).
// MODE 0: f32 out.  MODE 1: fp16 out.
// ===========================================================================
#define GPITCH 72                           // 64 halfs + 8 pad (conflict-free ldmatrix)
#define GARR_E (128 * GPITCH)               // 9216 elems per array
#define GSTAGE_E (2 * GARR_E)               // A + B = 18432 elems
#define GSMEM_BYTES (3 * GSTAGE_E * 2)      // 110592 B; 2 CTAs = 216 KB < 228 KB

__device__ __forceinline__ void gemm_produce(
    uint32_t smb, int stage,
    const __half* __restrict__ A, const __half* __restrict__ B,
    int row0, int col0, int k0, int tid)
{
#pragma unroll
    for (int i = 0; i < 8; ++i) {
        int id  = tid + i * 256;          // 0..2047
        int arr = id >> 10;               // 0:A 1:B
        int rid = (id >> 3) & 127;
        int cc  = id & 7;
        const __half* g = arr ? B : A;
        int grow = (arr ? col0 : row0) + rid;
        const __half* src = g + (size_t)grow * E_DIM + k0 + cc * 8;
        uint32_t dst = smb + (uint32_t)(stage * GSTAGE_E + arr * GARR_E + rid * GPITCH + cc * 8) * 2;
        CP_ASYNC16(dst, src);
    }
}

template <int MODE>
__device__ __forceinline__ void gemm_cp(
    const __half* __restrict__ A, const __half* __restrict__ B,
    const float* __restrict__ bias, float alpha,
    float* __restrict__ Cf, __half* __restrict__ Ch)
{
    extern __shared__ char dynsm[];
    const uint32_t smb = smem_u32(dynsm);
    const int tid  = threadIdx.x;
    const int lane = tid & 31;
    const int wid  = tid >> 5;
    const int wy   = wid >> 2;           // 0..1
    const int wx   = wid & 3;            // 0..3
    const int row0 = blockIdx.y * 128;
    const int col0 = blockIdx.x * 128;

    const int aOffE = (wy * 64 + (lane & 15)) * GPITCH + ((lane >> 4) & 1) * 8;
    const int bOffE = (wx * 32 + (lane & 7) + ((lane >> 4) & 1) * 8) * GPITCH + ((lane >> 3) & 1) * 8;

    float acc[4][4][4];
#pragma unroll
    for (int i = 0; i < 4; i++)
#pragma unroll
        for (int j = 0; j < 4; j++)
#pragma unroll
            for (int k = 0; k < 4; k++) acc[i][j][k] = 0.f;

    // prologue: chunks 0,1 into stages 0,1
    gemm_produce(smb, 0, A, B, row0, col0, 0, tid);
    CP_COMMIT();
    gemm_produce(smb, 1, A, B, row0, col0, 64, tid);
    CP_COMMIT();

    for (int c = 0; c < 16; ++c) {
        CP_WAIT(1);          // chunk c complete (one non-empty group per iter)
        __syncthreads();     // visible block-wide; prior readers of target stage done
        // wrap-around produce keeps groups non-empty; tail writes never re-read
        gemm_produce(smb, (c + 2) % 3, A, B, row0, col0, ((c + 2) & 15) * 64, tid);
        CP_COMMIT();

        const uint32_t stA = smb + (uint32_t)((c % 3) * GSTAGE_E) * 2;
        const uint32_t aHb = stA;
        const uint32_t bHb = stA + GARR_E * 2;

#pragma unroll
        for (int kb = 0; kb < 4; ++kb) {
            uint32_t bh[4][2];
#pragma unroll
            for (int np = 0; np < 2; ++np) {
                int boe = bOffE + np * 16 * GPITCH + kb * 16;
                LDSM4(bh[2 * np][0], bh[2 * np][1], bh[2 * np + 1][0], bh[2 * np + 1][1],
                      bHb + boe * 2);
            }
#pragma unroll
            for (int mf = 0; mf < 4; ++mf) {
                uint32_t ah[4];
                int aoe = aOffE + mf * 16 * GPITCH + kb * 16;
                LDSM4(ah[0], ah[1], ah[2], ah[3], aHb + aoe * 2);
                MMA_F16(acc[mf][0], ah, bh[0][0], bh[0][1]);
                MMA_F16(acc[mf][1], ah, bh[1][0], bh[1][1]);
                MMA_F16(acc[mf][2], ah, bh[2][0], bh[2][1]);
                MMA_F16(acc[mf][3], ah, bh[3][0], bh[3][1]);
            }
        }
    }
    CP_WAIT(0);   // drain wrap-around produces before exit

    // epilogue
#pragma unroll
    for (int mf = 0; mf < 4; ++mf) {
        int r = row0 + wy * 64 + mf * 16 + (lane >> 2);
#pragma unroll
        for (int nf = 0; nf < 4; ++nf) {
            int col = col0 + wx * 32 + nf * 8 + ((lane & 3) << 1);
            float b0 = bias[col], b1 = bias[col + 1];
            float v0 = (acc[mf][nf][0] + b0) * alpha;
            float v1 = (acc[mf][nf][1] + b1) * alpha;
            float v2 = (acc[mf][nf][2] + b0) * alpha;
            float v3 = (acc[mf][nf][3] + b1) * alpha;
            if (MODE == 0) {
                *(float2*)(Cf + (size_t)r * E_DIM + col)       = make_float2(v0, v1);
                *(float2*)(Cf + (size_t)(r + 8) * E_DIM + col) = make_float2(v2, v3);
            } else {
                *(uint32_t*)(Ch + (size_t)r * E_DIM + col)       = pack_h2(v0, v1);
                *(uint32_t*)(Ch + (size_t)(r + 8) * E_DIM + col) = pack_h2(v2, v3);
            }
        }
    }
}

__global__ void __launch_bounds__(256, 2)
qkv_kernel(const float* __restrict__ bq, const float* __restrict__ bk,
           const float* __restrict__ bv)
{
    const int z = blockIdx.z;
    const __half* Bh = gW + ((size_t)z << 20);
    // Q carries Dh^-0.5 * log2(e) so flash softmax works in exp2 domain
    if (z == 0)      gemm_cp<1>(gX, Bh, bq, 0.125f * 1.44269504f, nullptr, gQ);
    else if (z == 1) gemm_cp<1>(gX, Bh, bk, 1.0f, nullptr, gK);
    else             gemm_cp<1>(gX, Bh, bv, 1.0f, nullptr, gV);
}

__global__ void __launch_bounds__(256, 2)
oproj_kernel(const float* __restrict__ bo, float* __restrict__ out)
{
    gemm_cp<0>(gA, gW + ((size_t)3 << 20), bo, 1.0f, out, nullptr);
}

// ===========================================================================
// Flash attention (causal), fp16 Q/K/V, exp2-domain softmax — UNCHANGED from
// R11 (measured at its HMMA floor; protect it).
// ===========================================================================
#define FPITCH 72
#define FQ_E   (128 * FPITCH)              // 9216
#define FKV_E  (64 * FPITCH)               // 4608 per array
#define FSTAGE_E (2 * FKV_E)               // K + V per stage
#define FKV0_E FQ_E
#define FSMEM_BYTES ((FKV0_E + 3 * FSTAGE_E) * 2)   // 73728

__device__ __forceinline__ void flash_kv_produce(uint32_t smb, int stage, int j0,
                                                 int b, int colbase, int tid)
{
#pragma unroll
    for (int i = 0; i < 4; ++i) {
        int id  = tid + i * 256;          // 0..1023
        int arr = id >> 9;                // 0:K 1:V
        int rid = (id >> 3) & 63;
        int cc  = id & 7;
        const __half* g = arr ? gV : gK;
        const __half* src = g + ((size_t)(j0 + rid) * B_DIM + b) * E_DIM + colbase + cc * 8;
        uint32_t dst = smb + (uint32_t)(FKV0_E + stage * FSTAGE_E + arr * FKV_E + rid * FPITCH + cc * 8) * 2;
        CP_ASYNC16(dst, src);
    }
}

__device__ __forceinline__ void flash_one(int qt, uint32_t smb, int b, int colbase,
                                          int tid, int lane, int w,
                                          int qOffE, int kOffE, int vOffE)
{
    const int i0 = qt * 128;
    const int ktmax = 2 * qt + 1;         // >= 1 always

    // prologue: group0 = Q + kv0; group1 = kv1
#pragma unroll
    for (int i = 0; i < 4; ++i) {
        int id  = tid + i * 256;          // 0..1023
        int rid = id >> 3;
        int cc  = id & 7;
        const __half* src = gQ + ((size_t)(i0 + rid) * B_DIM + b) * E_DIM + colbase + cc * 8;
        uint32_t dst = smb + (uint32_t)(rid * FPITCH + cc * 8) * 2;
        CP_ASYNC16(dst, src);
    }
    flash_kv_produce(smb, 0, 0, b, colbase, tid);
    CP_COMMIT();
    flash_kv_produce(smb, 1, 64, b, colbase, tid);
    CP_COMMIT();

    float s_m[2] = {-1e9f, -1e9f};
    float s_l[2] = {0.f, 0.f};
    float o[8][4];
#pragma unroll
    for (int i = 0; i < 8; i++)
#pragma unroll
        for (int j = 0; j < 4; j++) o[i][j] = 0.f;

    const int rg0 = i0 + w * 16 + (lane >> 2);
    const uint32_t qB = smb;

    for (int kt = 0; kt <= ktmax; ++kt) {
        CP_WAIT(1);           // tile kt landed (one non-empty group per iter)
        __syncthreads();
        {   // wrap-around produce (clamped index; unread duplicates at tail)
            int ktn = (kt + 2 <= ktmax) ? (kt + 2) : ktmax;
            flash_kv_produce(smb, (kt + 2) % 3, ktn * 64, b, colbase, tid);
            CP_COMMIT();
        }

        const int j0 = kt * 64;
        const uint32_t stKV = smb + (uint32_t)(FKV0_E + (kt % 3) * FSTAGE_E) * 2;
        const uint32_t kB = stKV;
        const uint32_t vB = stKV + FKV_E * 2;

        // ---- S = Q @ K^T (single term, log2-domain scores) ----
        float s[8][4];
#pragma unroll
        for (int i = 0; i < 8; i++)
#pragma unroll
            for (int j = 0; j < 4; j++) s[i][j] = 0.f;

#pragma unroll
        for (int kb = 0; kb < 4; ++kb) {
            uint32_t a[4];
            LDSM4(a[0], a[1], a[2], a[3], qB + (qOffE + kb * 16) * 2);
            uint32_t kh[4][4];
#pragma unroll
            for (int np = 0; np < 4; ++np) {
                int boe = kOffE + np * 16 * FPITCH + kb * 16;
                LDSM4(kh[np][0], kh[np][1], kh[np][2], kh[np][3], kB + boe * 2);
            }
#pragma unroll
            for (int np = 0; np < 4; ++np) {
                MMA_F16(s[2 * np],     a, kh[np][0], kh[np][1]);
                MMA_F16(s[2 * np + 1], a, kh[np][2], kh[np][3]);
            }
        }

        // ---- causal mask ----
        if (j0 + 63 > i0 + w * 16) {
#pragma unroll
            for (int nf = 0; nf < 8; ++nf) {
                int j = j0 + nf * 8 + ((lane & 3) << 1);
                if (j     > rg0)     s[nf][0] = -1e9f;
                if (j + 1 > rg0)     s[nf][1] = -1e9f;
                if (j     > rg0 + 8) s[nf][2] = -1e9f;
                if (j + 1 > rg0 + 8) s[nf][3] = -1e9f;
            }
        }

        // ---- online softmax in exp2 domain ----
        float vmax[2];
#pragma unroll
        for (int half = 0; half < 2; ++half) {
            const int e0 = half * 2, e1 = half * 2 + 1;
            float m = -1e9f;
#pragma unroll
            for (int nf = 0; nf < 8; ++nf)
                m = fmaxf(m, fmaxf(s[nf][e0], s[nf][e1]));
            m = fmaxf(m, __shfl_xor_sync(0xffffffffu, m, 1));
            m = fmaxf(m, __shfl_xor_sync(0xffffffffu, m, 2));
            vmax[half] = m;
        }
        // warp-uniform skip: if max didn't move anywhere in this warp,
        // corr == 1 exactly -> no o-rescale, no corr-exp.
        const bool noresc = __all_sync(0xffffffffu,
                                       vmax[0] <= s_m[0] && vmax[1] <= s_m[1]);
#pragma unroll
        for (int half = 0; half < 2; ++half) {
            const int e0 = half * 2, e1 = half * 2 + 1;
            const float mnew = noresc ? s_m[half] : fmaxf(s_m[half], vmax[half]);
            float rsum = 0.f;
#pragma unroll
            for (int nf = 0; nf < 8; ++nf) {
                // hybrid: half the exps on MUFU (idle pipe), half on FMA poly
                float p0 = mufu_exp2(s[nf][e0] - mnew);
                float p1 = fast_exp2(s[nf][e1] - mnew);
                s[nf][e0] = p0; s[nf][e1] = p1;
                rsum += p0 + p1;
            }
            rsum += __shfl_xor_sync(0xffffffffu, rsum, 1);
            rsum += __shfl_xor_sync(0xffffffffu, rsum, 2);
            if (noresc) {
                s_l[half] += rsum;
            } else {
                float corr = fast_exp2(s_m[half] - mnew);
                s_l[half] = s_l[half] * corr + rsum;
                s_m[half] = mnew;
#pragma unroll
                for (int nf = 0; nf < 8; ++nf) {
                    o[nf][e0] *= corr;
                    o[nf][e1] *= corr;
                }
            }
        }

        // ---- O += P @ V (single term; P rounded at pack) ----
#pragma unroll
        for (int kc = 0; kc < 4; ++kc) {
            uint32_t ph[4];
            ph[0] = pack_h2(s[2 * kc][0],     s[2 * kc][1]);
            ph[1] = pack_h2(s[2 * kc][2],     s[2 * kc][3]);
            ph[2] = pack_h2(s[2 * kc + 1][0], s[2 * kc + 1][1]);
            ph[3] = pack_h2(s[2 * kc + 1][2], s[2 * kc + 1][3]);
            uint32_t wh[4][4];
#pragma unroll
            for (int np = 0; np < 4; ++np) {
                int voe = vOffE + kc * 16 * FPITCH + np * 16;
                LDSM4T(wh[np][0], wh[np][1], wh[np][2], wh[np][3], vB + voe * 2);
            }
#pragma unroll
            for (int np = 0; np < 4; ++np) {
                MMA_F16(o[2 * np],     ph, wh[np][0], wh[np][1]);
                MMA_F16(o[2 * np + 1], ph, wh[np][2], wh[np][3]);
            }
        }
    }
    CP_WAIT(0);        // drain wrap-around produces (next call reuses stages)
    __syncthreads();   // smem reads done before caller refills Q region

    // ---- finalize: attn = o / l, stored as fp16 ----
    const float inv0 = 1.f / s_l[0];
    const float inv1 = 1.f / s_l[1];
#pragma unroll
    for (int nf = 0; nf < 8; ++nf) {
        int col = colbase + nf * 8 + ((lane & 3) << 1);
        size_t r0off = ((size_t)rg0 * B_DIM + b) * E_DIM + col;
        size_t r1off = ((size_t)(rg0 + 8) * B_DIM + b) * E_DIM + col;
        *(uint32_t*)(gA + r0off) = pack_h2(o[nf][0] * inv0, o[nf][1] * inv0);
        *(uint32_t*)(gA + r1off) = pack_h2(o[nf][2] * inv1, o[nf][3] * inv1);
    }
}

__global__ void __launch_bounds__(256)
flash_mma_kernel()
{
    extern __shared__ char dynsm[];
    const uint32_t smb = smem_u32(dynsm);

    const int tid  = threadIdx.x;
    const int lane = tid & 31;
    const int w    = tid >> 5;
    const int pair = blockIdx.x;          // 0..7
    const int head = blockIdx.y;          // 0..31
    const int b    = head >> 4;
    const int h    = head & 15;
    const int colbase = h * DH;

    const int qOffE = (w * 16 + (lane & 15)) * FPITCH + ((lane >> 4) & 1) * 8;
    const int kOffE = ((lane & 7) + ((lane >> 4) & 1) * 8) * FPITCH + ((lane >> 3) & 1) * 8;
    const int vOffE = ((lane & 7) + ((lane >> 3) & 1) * 8) * FPITCH + ((lane >> 4) & 1) * 8;

    flash_one(pair,      smb, b, colbase, tid, lane, w, qOffE, kOffE, vOffE);
    flash_one(15 - pair, smb, b, colbase, tid, lane, w, qOffE, kOffE, vOffE);
}

// ===========================================================================
// kernel_launch
// Inputs: query, Wq, bq, Wk, bk, Wv, bv, Wo, bo, attn_mask (ignored: causal)
// ===========================================================================
extern "C" void kernel_launch(void* const* d_in, const int* in_sizes, int n_in,
                              void* d_out, int out_size)
{
    const float* query = (const float*)d_in[0];
    const float* Wq    = (const float*)d_in[1];
    const float* bq    = (const float*)d_in[2];
    const float* Wk    = (const float*)d_in[3];
    const float* bk    = (const float*)d_in[4];
    const float* Wv    = (const float*)d_in[5];
    const float* bv    = (const float*)d_in[6];
    const float* Wo    = (const float*)d_in[7];
    const float* bo    = (const float*)d_in[8];
    float* out = (float*)d_out;

    cudaFuncSetAttribute(qkv_kernel, cudaFuncAttributeMaxDynamicSharedMemorySize, GSMEM_BYTES);
    cudaFuncSetAttribute(oproj_kernel, cudaFuncAttributeMaxDynamicSharedMemorySize, GSMEM_BYTES);
    cudaFuncSetAttribute(flash_mma_kernel, cudaFuncAttributeMaxDynamicSharedMemorySize, FSMEM_BYTES);

    // X and weights -> fp16
    convert_kernel<<<8192, 256>>>(query, Wq, Wk, Wv, Wo);

    // QKV projections (all 1-term) -> fp16 q,k,v
    qkv_kernel<<<dim3(E_DIM / 128, MROWS / 128, 3), 256, GSMEM_BYTES>>>(bq, bk, bv);

    // causal flash attention: 8 balanced q-tile pairs x 32 heads
    flash_mma_kernel<<<dim3(8, B_DIM * H_DIM), 256, FSMEM_BYTES>>>();

    // output projection -> f32 out
    oproj_kernel<<<dim3(E_DIM / 128, MROWS / 128), 256, GSMEM_BYTES>>>(bo, out);
}